// round 11
// baseline (speedup 1.0000x reference)
#include <cuda_runtime.h>
#include <cuda.h>
#include <cuda_bf16.h>
#include <math.h>

#define BATCH 2
#define CH    128
#define HH    64
#define WW    64
#define QPB   9216
#define NQ    18432
#define NHEAD 4
#define KWIN  7
#define KAREA 49

// ---------------- scratch (static device memory; no allocation) ----------------
__device__ float g_ft[BATCH*HH*WW*CH];          // feat NHWC (for skip)
__device__ float g_fq[BATCH*HH*WW*CH];          // conv q NHWC
__device__ float g_fk[BATCH*HH*WW*CH];          // conv k NHWC
__device__ float g_fv[BATCH*HH*WW*CH];          // conv v NHWC
// input, TMA layout: [cic(2)][b(2)][y(64)][x(64)][c64]
__device__ __align__(1024) __nv_bfloat16 g_xh2[2*BATCH*HH*WW*64];
__device__ __align__(1024) __nv_bfloat16 g_xl2[2*BATCH*HH*WW*64];
// conv weights, TMA layout: [cic(2)][row=(z*9+kk)*128+co (3456)][ci64]
__device__ __align__(1024) __nv_bfloat16 g_wh2[2*3456*64];
__device__ __align__(1024) __nv_bfloat16 g_wl2[2*3456*64];
__device__ __nv_bfloat16 g_w0h[256*128];        // w0 [j][k] hi (k<128)
__device__ __nv_bfloat16 g_w0l[256*128];
__device__ __nv_bfloat16 g_w1h[128*256];        // w1 [o][k] hi
__device__ __nv_bfloat16 g_w1l[128*256];
__device__ float g_c0[2*256];                   // per-batch effective hidden bias
__device__ __nv_bfloat16 g_aggh[NQ*CH];         // attention output hi
__device__ __nv_bfloat16 g_aggl[NQ*CH];         // lo

static __device__ __forceinline__ void split_hl(float v, __nv_bfloat16& h, __nv_bfloat16& l) {
    h = __float2bfloat16_rn(v);
    l = __float2bfloat16_rn(v - __bfloat162float(h));
}

static __device__ __forceinline__ unsigned sptr(const void* p) {
    return (unsigned)__cvta_generic_to_shared(p);
}

#define CP_ASYNC16(dst, src, sz) \
    asm volatile("cp.async.cg.shared.global [%0], [%1], 16, %2;" :: "r"(dst), "l"(src), "r"(sz))
#define CP_COMMIT() asm volatile("cp.async.commit_group;")
#define CP_WAIT0()  asm volatile("cp.async.wait_group 0;")

#define LDMX4(r, addr) \
    asm volatile("ldmatrix.sync.aligned.m8n8.x4.shared.b16 {%0,%1,%2,%3}, [%4];" \
                 : "=r"((r)[0]), "=r"((r)[1]), "=r"((r)[2]), "=r"((r)[3]) : "r"(addr))

#define MMA16816(d, a, b0v, b1v) \
    asm volatile("mma.sync.aligned.m16n8k16.row.col.f32.bf16.bf16.f32 " \
                 "{%0,%1,%2,%3},{%4,%5,%6,%7},{%8,%9},{%0,%1,%2,%3};" \
                 : "+f"((d)[0]), "+f"((d)[1]), "+f"((d)[2]), "+f"((d)[3]) \
                 : "r"((a)[0]), "r"((a)[1]), "r"((a)[2]), "r"((a)[3]), "r"(b0v), "r"(b1v))

static __device__ __forceinline__ void mbar_wait(unsigned mbar, unsigned parity) {
    asm volatile(
        "{\n\t.reg .pred P;\n\t"
        "WL_%=:\n\t"
        "mbarrier.try_wait.parity.acquire.cta.shared::cta.b64 P, [%0], %1, 0x989680;\n\t"
        "@P bra.uni WD_%=;\n\t"
        "bra.uni WL_%=;\n\t"
        "WD_%=:\n\t}"
        :: "r"(mbar), "r"(parity) : "memory");
}

// ---------------- prep kernels ----------------
__global__ void prep_w_kernel(const float* __restrict__ qw,
                              const float* __restrict__ kw,
                              const float* __restrict__ vw) {
    int idx = blockIdx.x * blockDim.x + threadIdx.x;
    if (idx >= 3 * 9 * CH * CH) return;
    int ci = idx & 127;
    int co = (idx >> 7) & 127;
    int kk = (idx >> 14) % 9;
    int z  = idx / (9 * CH * CH);
    const float* w = (z == 0) ? qw : ((z == 1) ? kw : vw);
    float v = w[(co * CH + ci) * 9 + kk];
    int row = (z * 9 + kk) * 128 + co;
    int off = (ci >> 6) * (3456 * 64) + row * 64 + (ci & 63);
    split_hl(v, g_wh2[off], g_wl2[off]);
}

__global__ void prep_x_kernel(const float* __restrict__ x) {
    int idx = blockIdx.x * blockDim.x + threadIdx.x;
    if (idx >= BATCH * HH * WW * CH) return;
    int c = idx & 127;
    int p = (idx >> 7) & 4095;
    int b = idx >> 19;
    float v = x[(b * CH + c) * (HH * WW) + p];
    g_ft[idx] = v;
    int off = ((((c >> 6) * 2 + b) * 4096) + p) * 64 + (c & 63);
    split_hl(v, g_xh2[off], g_xl2[off]);
}

__global__ void prep_small_kernel(const float* __restrict__ w0,
                                  const float* __restrict__ b0,
                                  const float* __restrict__ w1,
                                  const float* __restrict__ cell) {
    int idx = blockIdx.x * blockDim.x + threadIdx.x;
    if (idx < 32768) {
        int j = idx >> 7, k = idx & 127;
        split_hl(w0[j * 130 + k], g_w0h[idx], g_w0l[idx]);
    } else if (idx < 65536) {
        int r = idx - 32768;
        split_hl(w1[r], g_w1h[r], g_w1l[r]);
    } else if (idx < 66048) {
        int r = idx - 65536;
        int b = r / 256, j = r % 256;
        float rc0 = cell[b * 2 + 0] * 64.0f;
        float rc1 = cell[b * 2 + 1] * 64.0f;
        g_c0[r] = b0[j] + w0[j * 130 + 128] * rc0 + w0[j * 130 + 129] * rc1;
    }
}

// ---------------- conv3x3: TMA 2-stage ring, 2 CTAs/SM, split-bf16 mma ----------------
#define CONV_STAGE 49152
#define CONV_SMEM  (2*CONV_STAGE)
#define CONV_SMEM_ALLOC (CONV_SMEM + 1024)

__device__ __forceinline__ void conv_issue(int s, unsigned dstb, unsigned mbar,
                                           const CUtensorMap* mxh, const CUtensorMap* mxl,
                                           const CUtensorMap* mwh, const CUtensorMap* mwl,
                                           int b, int yt, int z, int nhalf) {
    int kk = s >> 1, cic = s & 1;
    int dy = kk / 3 - 1, dx = kk - (kk / 3) * 3 - 1;
    int ycoord = 2 * yt + dy;
    int wrow = (z * 9 + kk) * 128 + nhalf * 64;
    asm volatile("mbarrier.arrive.expect_tx.shared.b64 _, [%0], %1;"
                 :: "r"(mbar), "r"(49152) : "memory");
#define TMA5D(dst, map, c0, c1, c2, c3, c4) \
    asm volatile("cp.async.bulk.tensor.5d.shared::cta.global.tile.mbarrier::complete_tx::bytes " \
                 "[%0], [%1, {%2,%3,%4,%5,%6}], [%7];" \
                 :: "r"(dst), "l"(map), "r"(c0), "r"(c1), "r"(c2), "r"(c3), "r"(c4), "r"(mbar) : "memory")
#define TMA3D(dst, map, c0, c1, c2) \
    asm volatile("cp.async.bulk.tensor.3d.shared::cta.global.tile.mbarrier::complete_tx::bytes " \
                 "[%0], [%1, {%2,%3,%4}], [%5];" \
                 :: "r"(dst), "l"(map), "r"(c0), "r"(c1), "r"(c2), "r"(mbar) : "memory")
    TMA5D(dstb,          mxh, 0, dx, ycoord, b, cic);
    TMA5D(dstb + 16384u, mxl, 0, dx, ycoord, b, cic);
    TMA3D(dstb + 32768u, mwh, 0, wrow, cic);
    TMA3D(dstb + 40960u, mwl, 0, wrow, cic);
#undef TMA5D
#undef TMA3D
}

__global__ __launch_bounds__(256, 2) void convtma_kernel(
    const __grid_constant__ CUtensorMap mxh,
    const __grid_constant__ CUtensorMap mxl,
    const __grid_constant__ CUtensorMap mwh,
    const __grid_constant__ CUtensorMap mwl,
    const float* __restrict__ qb,
    const float* __restrict__ kb,
    const float* __restrict__ vb) {
    extern __shared__ char smc[];
    __shared__ __align__(8) unsigned long long s_mbar[2];

    int t = threadIdx.x;
    int lane = t & 31;
    int w = t >> 5;
    int yt = blockIdx.x;
    int b  = blockIdx.y;
    int zz = blockIdx.z;
    int z  = zz >> 1;
    int nhalf = zz & 1;

    const float* bias = (z == 0) ? qb : ((z == 1) ? kb : vb);
    float* outp = (z == 0) ? g_fq : ((z == 1) ? g_fk : g_fv);

    int Mbase = (w >> 1) * 32;
    int Nbase = (w & 1) * 32;
    unsigned sb = (sptr(smc) + 1023u) & ~1023u;
    unsigned mb0 = sptr(s_mbar);

    if (t == 0) {
#pragma unroll
        for (int i = 0; i < 2; i++)
            asm volatile("mbarrier.init.shared.b64 [%0], 1;" :: "r"(mb0 + i * 8) : "memory");
        asm volatile("fence.proxy.async.shared::cta;" ::: "memory");
    }
    __syncthreads();

    if (t == 0) {
        conv_issue(0, sb, mb0, &mxh, &mxl, &mwh, &mwl, b, yt, z, nhalf);
        conv_issue(1, sb + CONV_STAGE, mb0 + 8, &mxh, &mxl, &mwh, &mwl, b, yt, z, nhalf);
    }

    float acc[2][4][4];
#pragma unroll
    for (int mi = 0; mi < 2; mi++)
#pragma unroll
        for (int ni = 0; ni < 4; ni++)
#pragma unroll
            for (int r = 0; r < 4; r++) acc[mi][ni][r] = 0.0f;

    int arow = (lane & 15);
    int acolb = ((lane >> 4) << 3) * 2;
    int brow = ((lane >> 4) << 3) + (lane & 7);
    int bcolb = (((lane >> 3) & 1) * 8) * 2;

    for (int s = 0; s < 18; s++) {
        int slot = s & 1;
        mbar_wait(mb0 + slot * 8, (unsigned)((s >> 1) & 1));
        unsigned bufb = sb + (unsigned)slot * CONV_STAGE;
#pragma unroll
        for (int ksub = 0; ksub < 4; ksub++) {
            unsigned ah[2][4], al[2][4];
#pragma unroll
            for (int mi = 0; mi < 2; mi++) {
                int p = Mbase + mi * 16 + arow;
                unsigned aoff = (unsigned)(p * 128 + ((acolb + ksub * 32) ^ ((p & 7) << 4)));
                LDMX4(ah[mi], bufb + aoff);
                LDMX4(al[mi], bufb + 16384u + aoff);
            }
#pragma unroll
            for (int nt = 0; nt < 2; nt++) {
                int n = Nbase + nt * 16 + brow;
                unsigned boff = (unsigned)(n * 128 + ((bcolb + ksub * 32) ^ ((n & 7) << 4)));
                unsigned bh[4], bl[4];
                LDMX4(bh, bufb + 32768u + boff);
                LDMX4(bl, bufb + 40960u + boff);
#pragma unroll
                for (int mi = 0; mi < 2; mi++) {
#pragma unroll
                    for (int h = 0; h < 2; h++) {
                        float* d = acc[mi][nt * 2 + h];
                        MMA16816(d, ah[mi], bh[2 * h], bh[2 * h + 1]);
                        MMA16816(d, ah[mi], bl[2 * h], bl[2 * h + 1]);
                        MMA16816(d, al[mi], bh[2 * h], bh[2 * h + 1]);
                    }
                }
            }
        }
        __syncthreads();
        if (s + 2 < 18 && t == 0)
            conv_issue(s + 2, sb + (unsigned)slot * CONV_STAGE, mb0 + slot * 8,
                       &mxh, &mxl, &mwh, &mwl, b, yt, z, nhalf);
    }

    int rr = lane >> 2;
    int c2 = (lane & 3) * 2;
#pragma unroll
    for (int mi = 0; mi < 2; mi++) {
#pragma unroll
        for (int ni = 0; ni < 4; ni++) {
            int co = nhalf * 64 + Nbase + ni * 8 + c2;
            float b0v = bias[co], b1v = bias[co + 1];
#pragma unroll
            for (int rs = 0; rs < 2; rs++) {
                int p = Mbase + mi * 16 + rr + rs * 8;
                int r = p >> 6, xo = p & 63;
                float* o = outp + ((b * HH + yt * 2 + r) * WW + xo) * CH + co;
                *(float2*)o = make_float2(acc[mi][ni][rs * 2 + 0] + b0v,
                                          acc[mi][ni][rs * 2 + 1] + b1v);
            }
        }
    }
}

// ---------------- attention: 8x8 query tile per block, smem k/v tiles ----------------
// block 256 thr (8 warps); warp w handles query row qy0+w, 8 queries (sx loop).
// grid (12 tx, 12 ty, 2 b). smem: ktile + vtile, each 14x14 px x 128 f32 (zero-padded OOB).
#define ATTN_TPX   14
#define ATTN_TILEF (ATTN_TPX*ATTN_TPX*128)
#define ATTN_SMEM  (2*ATTN_TILEF*4)

__global__ __launch_bounds__(256, 1) void attn_kernel(const float* __restrict__ coord,
                                                      const float* __restrict__ pbw,
                                                      const float* __restrict__ pbb) {
    extern __shared__ float stile[];
    float* ktile = stile;
    float* vtile = stile + ATTN_TILEF;
    __shared__ float slog[8][NHEAD][KAREA];
    __shared__ float sbias[8][2][KWIN][NHEAD];
    __shared__ float spbw[NHEAD * 64];
    __shared__ float spbb[NHEAD];
    __shared__ int sbnd[4];   // miny, maxy, minx, maxx

    int t = threadIdx.x;
    int w = t >> 5;
    int lane = t & 31;
    int qx0 = blockIdx.x * 8;
    int qy0 = blockIdx.y * 8;
    int b   = blockIdx.z;

    if (t < NHEAD * 64) spbw[t] = pbw[t];
    if (t < NHEAD) spbb[t] = pbb[t];
    if (t == 0) { sbnd[0] = 1 << 30; sbnd[1] = -(1 << 30); sbnd[2] = 1 << 30; sbnd[3] = -(1 << 30); }
    __syncthreads();

    if (t < 64) {
        int q = b * QPB + (qy0 + (t >> 3)) * 96 + qx0 + (t & 7);
        float cy = coord[q * 2 + 0];
        float cx = coord[q * 2 + 1];
        float py = ((cy + 1.0f) * 64.0f - 1.0f) * 0.5f;
        float px = ((cx + 1.0f) * 64.0f - 1.0f) * 0.5f;
        int iy0 = (int)rintf(py), ix0 = (int)rintf(px);
        atomicMin(&sbnd[0], iy0); atomicMax(&sbnd[1], iy0);
        atomicMin(&sbnd[2], ix0); atomicMax(&sbnd[3], ix0);
    }
    __syncthreads();
    int base_y = sbnd[0] - 3;
    int base_x = sbnd[2] - 3;
    int rows = min(sbnd[1] - sbnd[0], ATTN_TPX - 7) + 7;
    int cols = min(sbnd[3] - sbnd[2], ATTN_TPX - 7) + 7;

    // cooperative zero-padded fill of k/v tiles
    int ntask = rows * cols * 32;   // float4 slots per tile
    for (int i = t; i < 2 * ntask; i += 256) {
        int which = i >= ntask;
        int idx = which ? i - ntask : i;
        int px4 = idx >> 5, seg = idx & 31;
        int r = px4 / cols, c = px4 - r * cols;
        int gy = base_y + r, gx = base_x + c;
        float4 v = make_float4(0.f, 0.f, 0.f, 0.f);
        if ((unsigned)gy < 64u && (unsigned)gx < 64u)
            v = *(const float4*)((which ? g_fv : g_fk) + ((b * HH + gy) * WW + gx) * CH + seg * 4);
        *(float4*)((which ? vtile : ktile) + px4 * 128 + seg * 4) = v;
    }
    __syncthreads();

    int h = lane >> 3;
    int qy = qy0 + w;
    const float scale = 0.17677669529663687f;

    for (int sx = 0; sx < 8; sx++) {
        int q = b * QPB + qy * 96 + qx0 + sx;
        float cy = coord[q * 2 + 0];
        float cx = coord[q * 2 + 1];
        float py = ((cy + 1.0f) * 64.0f - 1.0f) * 0.5f;
        float px = ((cx + 1.0f) * 64.0f - 1.0f) * 0.5f;
        float riy = rintf(py), rix = rintf(px);
        int iy0 = (int)riy, ix0 = (int)rix;
        float fy = py - riy, fx = px - rix;

        // bilinear q sample (zeros padding), 4 channels per lane
        float qv0 = 0.f, qv1 = 0.f, qv2 = 0.f, qv3 = 0.f;
        {
            float yf = floorf(py), xf = floorf(px);
            int y0 = (int)yf, x0 = (int)xf;
            float wy1 = py - yf, wx1 = px - xf;
#pragma unroll
            for (int dy2 = 0; dy2 < 2; dy2++)
#pragma unroll
                for (int dx2 = 0; dx2 < 2; dx2++) {
                    int iy = y0 + dy2, ix = x0 + dx2;
                    if ((unsigned)iy < 64u && (unsigned)ix < 64u) {
                        float wg = (dy2 ? wy1 : 1.0f - wy1) * (dx2 ? wx1 : 1.0f - wx1);
                        const float4 v = *(const float4*)(g_fq + (((b * HH + iy) * WW + ix) * CH + 4 * lane));
                        qv0 += wg * v.x; qv1 += wg * v.y; qv2 += wg * v.z; qv3 += wg * v.w;
                    }
                }
        }

        // separable positional bias: lanes 0..13
        if (lane < 14) {
            int a = lane / 7;
            int dpos = lane - a * 7;
            float rel = 2.0f * ((a ? fx : fy) - (float)(dpos - 3));
            float a0 = 0.f, a1 = 0.f, a2 = 0.f, a3 = 0.f;
            const float step = 10.0f / 15.0f;
#pragma unroll
            for (int i = 0; i < 16; i++) {
                float fr = (i == 15) ? 1023.0f : (exp2f((float)i * step) - 1.0f);
                float s, c;
                sincosf(rel * fr, &s, &c);
                int si = a * 16 + i, ci2 = 32 + a * 16 + i;
                a0 += spbw[0 * 64 + si] * s + spbw[0 * 64 + ci2] * c;
                a1 += spbw[1 * 64 + si] * s + spbw[1 * 64 + ci2] * c;
                a2 += spbw[2 * 64 + si] * s + spbw[2 * 64 + ci2] * c;
                a3 += spbw[3 * 64 + si] * s + spbw[3 * 64 + ci2] * c;
            }
            if (a == 0) { a0 += spbb[0]; a1 += spbb[1]; a2 += spbb[2]; a3 += spbb[3]; }
            sbias[w][a][dpos][0] = a0; sbias[w][a][dpos][1] = a1;
            sbias[w][a][dpos][2] = a2; sbias[w][a][dpos][3] = a3;
        }
        __syncwarp();

        // logits from smem ktile (zero-padded => no bounds check)
        int lbase = (iy0 - base_y) * cols + (ix0 - base_x);
        {
            int k = 0;
            for (int dy = -3; dy <= 3; dy++) {
                for (int dx = -3; dx <= 3; dx++, k++) {
                    int li = lbase + dy * cols + dx;
                    const float4 kv = *(const float4*)(ktile + li * 128 + 4 * lane);
                    float dot = qv0 * kv.x + qv1 * kv.y + qv2 * kv.z + qv3 * kv.w;
                    dot += __shfl_xor_sync(0xffffffffu, dot, 1);
                    dot += __shfl_xor_sync(0xffffffffu, dot, 2);
                    dot += __shfl_xor_sync(0xffffffffu, dot, 4);
                    float lg = dot * scale + sbias[w][0][dy + 3][h] + sbias[w][1][dx + 3][h];
                    if ((lane & 7) == 0) slog[w][h][k] = lg;
                }
            }
        }
        __syncwarp();

        float mx = -1e30f;
        for (int kk = 0; kk < KAREA; kk++) mx = fmaxf(mx, slog[w][h][kk]);
        __syncwarp();
        float inv = 0.0f;
        if ((lane & 7) == 0) {
            float ssum = 0.0f;
            for (int kk = 0; kk < KAREA; kk++) {
                float e = expf(slog[w][h][kk] - mx);
                slog[w][h][kk] = e;
                ssum += e;
            }
            inv = 1.0f / ssum;
        }
        __syncwarp();
        inv = __shfl_sync(0xffffffffu, inv, (lane >> 3) << 3);

        // aggregate v from smem vtile
        float a0 = 0.f, a1 = 0.f, a2 = 0.f, a3 = 0.f;
        {
            int k = 0;
            for (int dy = -3; dy <= 3; dy++) {
                for (int dx = -3; dx <= 3; dx++, k++) {
                    int li = lbase + dy * cols + dx;
                    float wg = slog[w][h][k] * inv;
                    const float4 v = *(const float4*)(vtile + li * 128 + 4 * lane);
                    a0 += wg * v.x; a1 += wg * v.y; a2 += wg * v.z; a3 += wg * v.w;
                }
            }
        }

        int base = q * CH + 4 * lane;
        __nv_bfloat16 h0, l0, h1, l1, h2, l2, h3, l3;
        split_hl(a0, h0, l0); split_hl(a1, h1, l1);
        split_hl(a2, h2, l2); split_hl(a3, h3, l3);
        __nv_bfloat162 p;
        p.x = h0; p.y = h1; *(__nv_bfloat162*)(g_aggh + base) = p;
        p.x = h2; p.y = h3; *(__nv_bfloat162*)(g_aggh + base + 2) = p;
        p.x = l0; p.y = l1; *(__nv_bfloat162*)(g_aggl + base) = p;
        p.x = l2; p.y = l3; *(__nv_bfloat162*)(g_aggl + base + 2) = p;
        __syncwarp();
    }
}

// ---------------- MLP via split-bf16 mma, 128 q/block (single wave), cp.async ----------------
#define MLP_SMEM 208896
__global__ __launch_bounds__(512, 1) void mlpmma_kernel(const float* __restrict__ coord,
                                                        const float* __restrict__ b1,
                                                        float* __restrict__ out) {
    extern __shared__ char sm8[];
    unsigned sb = sptr(sm8);
    int t = threadIdx.x, lane = t & 31, w = t >> 5;
    int mw = w >> 2, nw = w & 3;
    int qbase = blockIdx.x * 128;
    int b = qbase / QPB;

    int arow = (lane & 15);
    int acoloff = ((lane >> 4) << 3);
    int brow = ((lane >> 4) << 3) + (lane & 7);
    int bcoloff = ((lane >> 3) & 1) * 8;

#pragma unroll
    for (int i = 0; i < 8; i++) {
        int e = t + i * 512;
        int half = e >> 11; int idx = e & 2047; int r = idx >> 4; int seg = idx & 15;
        const __nv_bfloat16* src = (half ? g_aggl : g_aggh) + (qbase + r) * 128 + seg * 8;
        CP_ASYNC16(sb + (unsigned)(half * 34816 + r * 272 + seg * 16), src, 16);
    }
#pragma unroll
    for (int i = 0; i < 16; i++) {
        int e = t + i * 512;
        int half = e >> 12; int idx = e & 4095; int j = idx >> 4; int seg = idx & 15;
        const __nv_bfloat16* src = (half ? g_w0l : g_w0h) + j * 128 + seg * 8;
        CP_ASYNC16(sb + (unsigned)(69632 + half * 69632 + j * 272 + seg * 16), src, 16);
    }
    CP_COMMIT();

    float acc1[2][8][4];
#pragma unroll
    for (int mi = 0; mi < 2; mi++)
#pragma unroll
        for (int n = 0; n < 8; n++)
#pragma unroll
            for (int r = 0; r < 4; r++) acc1[mi][n][r] = 0.0f;

    CP_WAIT0();
    __syncthreads();

#pragma unroll
    for (int ksub = 0; ksub < 8; ksub++) {
        unsigned ah[2][4], al[2][4];
        int kg = ksub * 16 + acoloff;
#pragma unroll
        for (int mi = 0; mi < 2; mi++) {
            unsigned aaddr = sb + (unsigned)((mw * 32 + mi * 16 + arow) * 272 + kg * 2);
            LDMX4(ah[mi], aaddr);
            LDMX4(al[mi], aaddr + 34816u);
        }
#pragma unroll
        for (int nt = 0; nt < 4; nt++) {
            unsigned baddr = sb + 69632u +
                (unsigned)((nw * 64 + nt * 16 + brow) * 272 + (bcoloff + ksub * 16) * 2);
            unsigned bh[4], bl[4];
            LDMX4(bh, baddr);
            LDMX4(bl, baddr + 69632u);
#pragma unroll
            for (int mi = 0; mi < 2; mi++)
#pragma unroll
                for (int h = 0; h < 2; h++) {
                    float* d = acc1[mi][nt * 2 + h];
                    MMA16816(d, ah[mi], bh[2 * h], bh[2 * h + 1]);
                    MMA16816(d, ah[mi], bl[2 * h], bl[2 * h + 1]);
                    MMA16816(d, al[mi], bh[2 * h], bh[2 * h + 1]);
                }
        }
    }
    __syncthreads();

#pragma unroll
    for (int i = 0; i < 8; i++) {
        int e = t + i * 512;
        int half = e >> 11; int idx = e & 2047; int o = idx >> 4; int seg = idx & 15;
        const __nv_bfloat16* src = (half ? g_w1l : g_w1h) + o * 256 + seg * 8;
        CP_ASYNC16(sb + (unsigned)(135168 + half * 34816 + o * 272 + seg * 16), src, 16);
    }
    CP_COMMIT();

    {
        int r0 = mw * 32 + (lane >> 2);
        int cb = nw * 64 + (lane & 3) * 2;
#pragma unroll
        for (int mi = 0; mi < 2; mi++) {
#pragma unroll
            for (int n = 0; n < 8; n++) {
                int c = cb + n * 8;
                float c0a = g_c0[b * 256 + c];
                float c0b = g_c0[b * 256 + c + 1];
#pragma unroll
                for (int rs = 0; rs < 2; rs++) {
                    float v0 = acc1[mi][n][rs * 2 + 0] + c0a;
                    float v1 = acc1[mi][n][rs * 2 + 1] + c0b;
                    float gl0 = 0.5f * v0 * (1.0f + erff(v0 * 0.70710678118654752f));
                    float gl1 = 0.5f * v1 * (1.0f + erff(v1 * 0.70710678118654752f));
                    __nv_bfloat16 h0, l0, h1, l1;
                    split_hl(gl0, h0, l0); split_hl(gl1, h1, l1);
                    int row = r0 + mi * 16 + rs * 8;
                    __nv_bfloat162 hp; hp.x = h0; hp.y = h1;
                    __nv_bfloat162 lp; lp.x = l0; lp.y = l1;
                    *(__nv_bfloat162*)(sm8 + row * 528 + c * 2) = hp;
                    *(__nv_bfloat162*)(sm8 + 67584 + row * 528 + c * 2) = lp;
                }
            }
        }
    }

    float acc2[2][2][2][4];
#pragma unroll
    for (int mi = 0; mi < 2; mi++)
#pragma unroll
        for (int nt = 0; nt < 2; nt++)
#pragma unroll
            for (int h = 0; h < 2; h++)
#pragma unroll
                for (int r = 0; r < 4; r++) acc2[mi][nt][h][r] = 0.0f;

    for (int kc = 0; kc < 2; kc++) {
        CP_WAIT0();
        __syncthreads();
#pragma unroll
        for (int ksub = 0; ksub < 8; ksub++) {
            unsigned ah[2][4], al[2][4];
            int kg = kc * 128 + ksub * 16 + acoloff;
#pragma unroll
            for (int mi = 0; mi < 2; mi++) {
                unsigned aaddr = sb + (unsigned)((mw * 32 + mi * 16 + arow) * 528 + kg * 2);
                LDMX4(ah[mi], aaddr);
                LDMX4(al[mi], aaddr + 67584u);
            }
#pragma unroll
            for (int nt = 0; nt < 2; nt++) {
                unsigned baddr = sb + 135168u +
                    (unsigned)((nw * 32 + nt * 16 + brow) * 272 + (bcoloff + ksub * 16) * 2);
                unsigned bh[4], bl[4];
                LDMX4(bh, baddr);
                LDMX4(bl, baddr + 34816u);
#pragma unroll
                for (int mi = 0; mi < 2; mi++)
#pragma unroll
                    for (int h = 0; h < 2; h++) {
                        float* d = acc2[mi][nt][h];
                        MMA16816(d, ah[mi], bh[2 * h], bh[2 * h + 1]);
                        MMA16816(d, ah[mi], bl[2 * h], bl[2 * h + 1]);
                        MMA16816(d, al[mi], bh[2 * h], bh[2 * h + 1]);
                    }
            }
        }
        if (kc == 0) {
            __syncthreads();
#pragma unroll
            for (int i = 0; i < 8; i++) {
                int e = t + i * 512;
                int half = e >> 11; int idx = e & 2047; int o = idx >> 4; int seg = idx & 15;
                const __nv_bfloat16* src = (half ? g_w1l : g_w1h) + o * 256 + 128 + seg * 8;
                CP_ASYNC16(sb + (unsigned)(135168 + half * 34816 + o * 272 + seg * 16), src, 16);
            }
            CP_COMMIT();
        }
    }

#pragma unroll
    for (int mi = 0; mi < 2; mi++) {
#pragma unroll
        for (int rs = 0; rs < 2; rs++) {
            int q = qbase + mw * 32 + mi * 16 + (lane >> 2) + rs * 8;
            float cy = coord[q * 2 + 0];
            float cx = coord[q * 2 + 1];
            float py = fminf(fmaxf(((cy + 1.0f) * 64.0f - 1.0f) * 0.5f, 0.0f), 63.0f);
            float px = fminf(fmaxf(((cx + 1.0f) * 64.0f - 1.0f) * 0.5f, 0.0f), 63.0f);
            float yf = floorf(py), xf = floorf(px);
            int y0 = (int)yf, x0 = (int)xf;
            float wy1 = py - yf, wx1 = px - xf;
            int y1 = min(y0 + 1, 63), x1 = min(x0 + 1, 63);
            float wts[4] = { (1.0f - wy1) * (1.0f - wx1), (1.0f - wy1) * wx1,
                             wy1 * (1.0f - wx1),          wy1 * wx1 };
            const float* fp0 = g_ft + ((b * HH + y0) * WW + x0) * CH;
            const float* fp1 = g_ft + ((b * HH + y0) * WW + x1) * CH;
            const float* fp2 = g_ft + ((b * HH + y1) * WW + x0) * CH;
            const float* fp3 = g_ft + ((b * HH + y1) * WW + x1) * CH;
#pragma unroll
            for (int nt = 0; nt < 2; nt++) {
#pragma unroll
                for (int h = 0; h < 2; h++) {
                    int c = nw * 32 + nt * 16 + h * 8 + (lane & 3) * 2;
                    float2 f0 = *(const float2*)(fp0 + c);
                    float2 f1 = *(const float2*)(fp1 + c);
                    float2 f2 = *(const float2*)(fp2 + c);
                    float2 f3 = *(const float2*)(fp3 + c);
                    float s0 = wts[0] * f0.x + wts[1] * f1.x + wts[2] * f2.x + wts[3] * f3.x;
                    float s1 = wts[0] * f0.y + wts[1] * f1.y + wts[2] * f2.y + wts[3] * f3.y;
                    float2 o;
                    o.x = acc2[mi][nt][h][rs * 2 + 0] + b1[c] + s0;
                    o.y = acc2[mi][nt][h][rs * 2 + 1] + b1[c + 1] + s1;
                    *(float2*)(out + q * CH + c) = o;
                }
            }
        }
    }
}

// ---------------- launch ----------------
typedef CUresult (*EncTiledFn)(CUtensorMap*, CUtensorMapDataType, cuuint32_t, void*,
                               const cuuint64_t*, const cuuint64_t*, const cuuint32_t*,
                               const cuuint32_t*, CUtensorMapInterleave, CUtensorMapSwizzle,
                               CUtensorMapL2promotion, CUtensorMapFloatOOBfill);

extern "C" void kernel_launch(void* const* d_in, const int* in_sizes, int n_in,
                              void* d_out, int out_size) {
    const float* x     = (const float*)d_in[0];
    const float* coord = (const float*)d_in[1];
    const float* cell  = (const float*)d_in[3];
    const float* qw    = (const float*)d_in[4];
    const float* qb    = (const float*)d_in[5];
    const float* kw    = (const float*)d_in[6];
    const float* kb    = (const float*)d_in[7];
    const float* vw    = (const float*)d_in[8];
    const float* vb    = (const float*)d_in[9];
    const float* pbw   = (const float*)d_in[10];
    const float* pbb   = (const float*)d_in[11];
    const float* w0    = (const float*)d_in[12];
    const float* b0    = (const float*)d_in[13];
    const float* w1    = (const float*)d_in[14];
    const float* b1    = (const float*)d_in[15];
    float* out = (float*)d_out;

    void* fp = nullptr;
    cudaGetDriverEntryPoint("cuTensorMapEncodeTiled", &fp, cudaEnableDefault, nullptr);
    EncTiledFn enc = (EncTiledFn)fp;

    void *pxh, *pxl, *pwh, *pwl;
    cudaGetSymbolAddress(&pxh, g_xh2);
    cudaGetSymbolAddress(&pxl, g_xl2);
    cudaGetSymbolAddress(&pwh, g_wh2);
    cudaGetSymbolAddress(&pwl, g_wl2);

    CUtensorMap mxh, mxl, mwh, mwl;
    {
        cuuint64_t dims[5]    = {64, 64, 64, 2, 2};
        cuuint64_t strides[4] = {128, 8192, 524288, 1048576};
        cuuint32_t box[5]     = {64, 64, 2, 1, 1};
        cuuint32_t es[5]      = {1, 1, 1, 1, 1};
        enc(&mxh, CU_TENSOR_MAP_DATA_TYPE_BFLOAT16, 5, pxh, dims, strides, box, es,
            CU_TENSOR_MAP_INTERLEAVE_NONE, CU_TENSOR_MAP_SWIZZLE_128B,
            CU_TENSOR_MAP_L2_PROMOTION_L2_128B, CU_TENSOR_MAP_FLOAT_OOB_FILL_NONE);
        enc(&mxl, CU_TENSOR_MAP_DATA_TYPE_BFLOAT16, 5, pxl, dims, strides, box, es,
            CU_TENSOR_MAP_INTERLEAVE_NONE, CU_TENSOR_MAP_SWIZZLE_128B,
            CU_TENSOR_MAP_L2_PROMOTION_L2_128B, CU_TENSOR_MAP_FLOAT_OOB_FILL_NONE);
    }
    {
        cuuint64_t dims[3]    = {64, 3456, 2};
        cuuint64_t strides[2] = {128, 442368};
        cuuint32_t box[3]     = {64, 64, 1};
        cuuint32_t es[3]      = {1, 1, 1};
        enc(&mwh, CU_TENSOR_MAP_DATA_TYPE_BFLOAT16, 3, pwh, dims, strides, box, es,
            CU_TENSOR_MAP_INTERLEAVE_NONE, CU_TENSOR_MAP_SWIZZLE_128B,
            CU_TENSOR_MAP_L2_PROMOTION_L2_128B, CU_TENSOR_MAP_FLOAT_OOB_FILL_NONE);
        enc(&mwl, CU_TENSOR_MAP_DATA_TYPE_BFLOAT16, 3, pwl, dims, strides, box, es,
            CU_TENSOR_MAP_INTERLEAVE_NONE, CU_TENSOR_MAP_SWIZZLE_128B,
            CU_TENSOR_MAP_L2_PROMOTION_L2_128B, CU_TENSOR_MAP_FLOAT_OOB_FILL_NONE);
    }

    prep_w_kernel<<<(3 * 9 * CH * CH + 255) / 256, 256>>>(qw, kw, vw);
    prep_x_kernel<<<(BATCH * HH * WW * CH + 255) / 256, 256>>>(x);
    prep_small_kernel<<<(66048 + 255) / 256, 256>>>(w0, b0, w1, cell);

    cudaFuncSetAttribute(convtma_kernel, cudaFuncAttributeMaxDynamicSharedMemorySize, CONV_SMEM_ALLOC);
    convtma_kernel<<<dim3(32, 2, 6), 256, CONV_SMEM_ALLOC>>>(mxh, mxl, mwh, mwl, qb, kb, vb);

    cudaFuncSetAttribute(attn_kernel, cudaFuncAttributeMaxDynamicSharedMemorySize, ATTN_SMEM);
    attn_kernel<<<dim3(12, 12, 2), 256, ATTN_SMEM>>>(coord, pbw, pbb);

    cudaFuncSetAttribute(mlpmma_kernel, cudaFuncAttributeMaxDynamicSharedMemorySize, MLP_SMEM);
    mlpmma_kernel<<<NQ / 128, 512, MLP_SMEM>>>(coord, b1, out);
}

// round 13
// speedup vs baseline: 1.3598x; 1.3598x over previous
#include <cuda_runtime.h>
#include <cuda.h>
#include <cuda_bf16.h>
#include <math.h>

#define BATCH 2
#define CH    128
#define HH    64
#define WW    64
#define QPB   9216
#define NQ    18432
#define NHEAD 4
#define KWIN  7
#define KAREA 49

// ---------------- scratch (static device memory; no allocation) ----------------
__device__ float g_ft[BATCH*HH*WW*CH];          // feat NHWC (for skip)
__device__ float g_fq[BATCH*HH*WW*CH];          // conv q NHWC
__device__ float g_fk[BATCH*HH*WW*CH];          // conv k NHWC
__device__ float g_fv[BATCH*HH*WW*CH];          // conv v NHWC
// input, TMA layout: [cic(2)][b(2)][y(64)][x(64)][c64]
__device__ __align__(1024) __nv_bfloat16 g_xh2[2*BATCH*HH*WW*64];
__device__ __align__(1024) __nv_bfloat16 g_xl2[2*BATCH*HH*WW*64];
// conv weights, TMA layout: [cic(2)][row=(z*9+kk)*128+co (3456)][ci64]
__device__ __align__(1024) __nv_bfloat16 g_wh2[2*3456*64];
__device__ __align__(1024) __nv_bfloat16 g_wl2[2*3456*64];
__device__ __nv_bfloat16 g_w0h[256*128];        // w0 [j][k] hi (k<128)
__device__ __nv_bfloat16 g_w0l[256*128];
__device__ __nv_bfloat16 g_w1h[128*256];        // w1 [o][k] hi
__device__ __nv_bfloat16 g_w1l[128*256];
__device__ float g_c0[2*256];                   // per-batch effective hidden bias
__device__ float g_fr16[16];                    // fp32 freqs
__device__ float g_pbA[16*14*4];                // angle-addition tables [i][a*7+d][h]
__device__ float g_pbB[16*14*4];
__device__ __nv_bfloat16 g_aggh[NQ*CH];         // attention output hi
__device__ __nv_bfloat16 g_aggl[NQ*CH];         // lo

static __device__ __forceinline__ void split_hl(float v, __nv_bfloat16& h, __nv_bfloat16& l) {
    h = __float2bfloat16_rn(v);
    l = __float2bfloat16_rn(v - __bfloat162float(h));
}

static __device__ __forceinline__ unsigned sptr(const void* p) {
    return (unsigned)__cvta_generic_to_shared(p);
}

#define CP_ASYNC16(dst, src, sz) \
    asm volatile("cp.async.cg.shared.global [%0], [%1], 16, %2;" :: "r"(dst), "l"(src), "r"(sz))
#define CP_COMMIT() asm volatile("cp.async.commit_group;")
#define CP_WAIT0()  asm volatile("cp.async.wait_group 0;")

#define LDMX4(r, addr) \
    asm volatile("ldmatrix.sync.aligned.m8n8.x4.shared.b16 {%0,%1,%2,%3}, [%4];" \
                 : "=r"((r)[0]), "=r"((r)[1]), "=r"((r)[2]), "=r"((r)[3]) : "r"(addr))

#define MMA16816(d, a, b0v, b1v) \
    asm volatile("mma.sync.aligned.m16n8k16.row.col.f32.bf16.bf16.f32 " \
                 "{%0,%1,%2,%3},{%4,%5,%6,%7},{%8,%9},{%0,%1,%2,%3};" \
                 : "+f"((d)[0]), "+f"((d)[1]), "+f"((d)[2]), "+f"((d)[3]) \
                 : "r"((a)[0]), "r"((a)[1]), "r"((a)[2]), "r"((a)[3]), "r"(b0v), "r"(b1v))

static __device__ __forceinline__ void mbar_wait(unsigned mbar, unsigned parity) {
    asm volatile(
        "{\n\t.reg .pred P;\n\t"
        "WL_%=:\n\t"
        "mbarrier.try_wait.parity.acquire.cta.shared::cta.b64 P, [%0], %1, 0x989680;\n\t"
        "@P bra.uni WD_%=;\n\t"
        "bra.uni WL_%=;\n\t"
        "WD_%=:\n\t}"
        :: "r"(mbar), "r"(parity) : "memory");
}

// ---------------- prep kernels ----------------
__global__ void prep_w_kernel(const float* __restrict__ qw,
                              const float* __restrict__ kw,
                              const float* __restrict__ vw) {
    int idx = blockIdx.x * blockDim.x + threadIdx.x;
    if (idx >= 3 * 9 * CH * CH) return;
    int ci = idx & 127;
    int co = (idx >> 7) & 127;
    int kk = (idx >> 14) % 9;
    int z  = idx / (9 * CH * CH);
    const float* w = (z == 0) ? qw : ((z == 1) ? kw : vw);
    float v = w[(co * CH + ci) * 9 + kk];
    int row = (z * 9 + kk) * 128 + co;
    int off = (ci >> 6) * (3456 * 64) + row * 64 + (ci & 63);
    split_hl(v, g_wh2[off], g_wl2[off]);
}

__global__ void prep_x_kernel(const float* __restrict__ x) {
    int idx = blockIdx.x * blockDim.x + threadIdx.x;
    if (idx >= BATCH * HH * WW * CH) return;
    int c = idx & 127;
    int p = (idx >> 7) & 4095;
    int b = idx >> 19;
    float v = x[(b * CH + c) * (HH * WW) + p];
    g_ft[idx] = v;
    int off = ((((c >> 6) * 2 + b) * 4096) + p) * 64 + (c & 63);
    split_hl(v, g_xh2[off], g_xl2[off]);
}

__global__ void prep_small_kernel(const float* __restrict__ w0,
                                  const float* __restrict__ b0,
                                  const float* __restrict__ w1,
                                  const float* __restrict__ cell,
                                  const float* __restrict__ pbw) {
    int idx = blockIdx.x * blockDim.x + threadIdx.x;
    if (idx < 32768) {
        int j = idx >> 7, k = idx & 127;
        split_hl(w0[j * 130 + k], g_w0h[idx], g_w0l[idx]);
    } else if (idx < 65536) {
        int r = idx - 32768;
        split_hl(w1[r], g_w1h[r], g_w1l[r]);
    } else if (idx < 66048) {
        int r = idx - 65536;
        int b = r / 256, j = r % 256;
        float rc0 = cell[b * 2 + 0] * 64.0f;
        float rc1 = cell[b * 2 + 1] * 64.0f;
        g_c0[r] = b0[j] + w0[j * 130 + 128] * rc0 + w0[j * 130 + 129] * rc1;
    } else if (idx < 66064) {
        int i = idx - 66048;
        const float step = 10.0f / 15.0f;
        g_fr16[i] = (i == 15) ? 1023.0f : (exp2f((float)i * step) - 1.0f);
    } else if (idx < 66064 + 2 * 16 * 14 * 4) {
        int r = idx - 66064;
        int half = r / 896;          // 0 = A, 1 = B
        int rr = r - half * 896;
        int i = rr / 56;
        int dd = (rr % 56) / 4;      // a*7 + dpos
        int h = rr & 3;
        int a = dd / 7, dpos = dd - a * 7;
        const float step = 10.0f / 15.0f;
        float fr = (i == 15) ? 1023.0f : (exp2f((float)i * step) - 1.0f);
        double phi = 2.0 * (double)(dpos - 3) * (double)fr;
        float cphi = (float)cos(phi);
        float sphi = (float)sin(phi);
        float ws = pbw[h * 64 + a * 16 + i];
        float wc = pbw[h * 64 + 32 + a * 16 + i];
        float val = half ? (wc * cphi - ws * sphi) : (ws * cphi + wc * sphi);
        (half ? g_pbB : g_pbA)[(i * 14 + dd) * 4 + h] = val;
    }
}

// ---------------- conv3x3: TMA 2-stage ring, 2 CTAs/SM, split-bf16 mma ----------------
#define CONV_STAGE 49152
#define CONV_SMEM  (2*CONV_STAGE)
#define CONV_SMEM_ALLOC (CONV_SMEM + 1024)

__device__ __forceinline__ void conv_issue(int s, unsigned dstb, unsigned mbar,
                                           const CUtensorMap* mxh, const CUtensorMap* mxl,
                                           const CUtensorMap* mwh, const CUtensorMap* mwl,
                                           int b, int yt, int z, int nhalf) {
    int kk = s >> 1, cic = s & 1;
    int dy = kk / 3 - 1, dx = kk - (kk / 3) * 3 - 1;
    int ycoord = 2 * yt + dy;
    int wrow = (z * 9 + kk) * 128 + nhalf * 64;
    asm volatile("mbarrier.arrive.expect_tx.shared.b64 _, [%0], %1;"
                 :: "r"(mbar), "r"(49152) : "memory");
#define TMA5D(dst, map, c0, c1, c2, c3, c4) \
    asm volatile("cp.async.bulk.tensor.5d.shared::cta.global.tile.mbarrier::complete_tx::bytes " \
                 "[%0], [%1, {%2,%3,%4,%5,%6}], [%7];" \
                 :: "r"(dst), "l"(map), "r"(c0), "r"(c1), "r"(c2), "r"(c3), "r"(c4), "r"(mbar) : "memory")
#define TMA3D(dst, map, c0, c1, c2) \
    asm volatile("cp.async.bulk.tensor.3d.shared::cta.global.tile.mbarrier::complete_tx::bytes " \
                 "[%0], [%1, {%2,%3,%4}], [%5];" \
                 :: "r"(dst), "l"(map), "r"(c0), "r"(c1), "r"(c2), "r"(mbar) : "memory")
    TMA5D(dstb,          mxh, 0, dx, ycoord, b, cic);
    TMA5D(dstb + 16384u, mxl, 0, dx, ycoord, b, cic);
    TMA3D(dstb + 32768u, mwh, 0, wrow, cic);
    TMA3D(dstb + 40960u, mwl, 0, wrow, cic);
#undef TMA5D
#undef TMA3D
}

__global__ __launch_bounds__(256, 2) void convtma_kernel(
    const __grid_constant__ CUtensorMap mxh,
    const __grid_constant__ CUtensorMap mxl,
    const __grid_constant__ CUtensorMap mwh,
    const __grid_constant__ CUtensorMap mwl,
    const float* __restrict__ qb,
    const float* __restrict__ kb,
    const float* __restrict__ vb) {
    extern __shared__ char smc[];
    __shared__ __align__(8) unsigned long long s_mbar[2];

    int t = threadIdx.x;
    int lane = t & 31;
    int w = t >> 5;
    int yt = blockIdx.x;
    int b  = blockIdx.y;
    int zz = blockIdx.z;
    int z  = zz >> 1;
    int nhalf = zz & 1;

    const float* bias = (z == 0) ? qb : ((z == 1) ? kb : vb);
    float* outp = (z == 0) ? g_fq : ((z == 1) ? g_fk : g_fv);

    int Mbase = (w >> 1) * 32;
    int Nbase = (w & 1) * 32;
    unsigned sb = (sptr(smc) + 1023u) & ~1023u;
    unsigned mb0 = sptr(s_mbar);

    if (t == 0) {
#pragma unroll
        for (int i = 0; i < 2; i++)
            asm volatile("mbarrier.init.shared.b64 [%0], 1;" :: "r"(mb0 + i * 8) : "memory");
        asm volatile("fence.proxy.async.shared::cta;" ::: "memory");
    }
    __syncthreads();

    if (t == 0) {
        conv_issue(0, sb, mb0, &mxh, &mxl, &mwh, &mwl, b, yt, z, nhalf);
        conv_issue(1, sb + CONV_STAGE, mb0 + 8, &mxh, &mxl, &mwh, &mwl, b, yt, z, nhalf);
    }

    float acc[2][4][4];
#pragma unroll
    for (int mi = 0; mi < 2; mi++)
#pragma unroll
        for (int ni = 0; ni < 4; ni++)
#pragma unroll
            for (int r = 0; r < 4; r++) acc[mi][ni][r] = 0.0f;

    int arow = (lane & 15);
    int acolb = ((lane >> 4) << 3) * 2;
    int brow = ((lane >> 4) << 3) + (lane & 7);
    int bcolb = (((lane >> 3) & 1) * 8) * 2;

    for (int s = 0; s < 18; s++) {
        int slot = s & 1;
        mbar_wait(mb0 + slot * 8, (unsigned)((s >> 1) & 1));
        unsigned bufb = sb + (unsigned)slot * CONV_STAGE;
#pragma unroll
        for (int ksub = 0; ksub < 4; ksub++) {
            unsigned ah[2][4], al[2][4];
#pragma unroll
            for (int mi = 0; mi < 2; mi++) {
                int p = Mbase + mi * 16 + arow;
                unsigned aoff = (unsigned)(p * 128 + ((acolb + ksub * 32) ^ ((p & 7) << 4)));
                LDMX4(ah[mi], bufb + aoff);
                LDMX4(al[mi], bufb + 16384u + aoff);
            }
#pragma unroll
            for (int nt = 0; nt < 2; nt++) {
                int n = Nbase + nt * 16 + brow;
                unsigned boff = (unsigned)(n * 128 + ((bcolb + ksub * 32) ^ ((n & 7) << 4)));
                unsigned bh[4], bl[4];
                LDMX4(bh, bufb + 32768u + boff);
                LDMX4(bl, bufb + 40960u + boff);
#pragma unroll
                for (int mi = 0; mi < 2; mi++) {
#pragma unroll
                    for (int h = 0; h < 2; h++) {
                        float* d = acc[mi][nt * 2 + h];
                        MMA16816(d, ah[mi], bh[2 * h], bh[2 * h + 1]);
                        MMA16816(d, ah[mi], bl[2 * h], bl[2 * h + 1]);
                        MMA16816(d, al[mi], bh[2 * h], bh[2 * h + 1]);
                    }
                }
            }
        }
        __syncthreads();
        if (s + 2 < 18 && t == 0)
            conv_issue(s + 2, sb + (unsigned)slot * CONV_STAGE, mb0 + slot * 8,
                       &mxh, &mxl, &mwh, &mwl, b, yt, z, nhalf);
    }

    int rr = lane >> 2;
    int c2 = (lane & 3) * 2;
#pragma unroll
    for (int mi = 0; mi < 2; mi++) {
#pragma unroll
        for (int ni = 0; ni < 4; ni++) {
            int co = nhalf * 64 + Nbase + ni * 8 + c2;
            float b0v = bias[co], b1v = bias[co + 1];
#pragma unroll
            for (int rs = 0; rs < 2; rs++) {
                int p = Mbase + mi * 16 + rr + rs * 8;
                int r = p >> 6, xo = p & 63;
                float* o = outp + ((b * HH + yt * 2 + r) * WW + xo) * CH + co;
                *(float2*)o = make_float2(acc[mi][ni][rs * 2 + 0] + b0v,
                                          acc[mi][ni][rs * 2 + 1] + b1v);
            }
        }
    }
}

// ---------------- attention: one warp per query, angle-addition pos-bias ----------------
__global__ __launch_bounds__(256) void attn_kernel(const float* __restrict__ coord,
                                                   const float* __restrict__ pbb) {
    __shared__ float slog[8][NHEAD][KAREA];
    __shared__ float sbias[8][2][KWIN][NHEAD];
    __shared__ float spbb[NHEAD];
    __shared__ float sfr[16];
    __shared__ float sA[16*14*4];
    __shared__ float sB[16*14*4];
    __shared__ float sth[8][2][16];
    __shared__ float cth[8][2][16];

    int t = threadIdx.x;
    int w = t >> 5;
    int lane = t & 31;
    if (t < NHEAD) spbb[t] = pbb[t];
    if (t < 16) sfr[t] = g_fr16[t];
    for (int i = t; i < 16 * 14 * 4; i += 256) { sA[i] = g_pbA[i]; sB[i] = g_pbB[i]; }
    __syncthreads();

    int q = blockIdx.x * 8 + w;
    int b = q / QPB;
    float cy = coord[q * 2 + 0];
    float cx = coord[q * 2 + 1];
    float py = ((cy + 1.0f) * 64.0f - 1.0f) * 0.5f;
    float px = ((cx + 1.0f) * 64.0f - 1.0f) * 0.5f;
    float riy = rintf(py), rix = rintf(px);
    int iy0 = (int)riy, ix0 = (int)rix;
    float fy = py - riy, fx = px - rix;
    int h = lane >> 3;

    float qv0 = 0.f, qv1 = 0.f, qv2 = 0.f, qv3 = 0.f;
    {
        float yf = floorf(py), xf = floorf(px);
        int y0 = (int)yf, x0 = (int)xf;
        float wy1 = py - yf, wx1 = px - xf;
#pragma unroll
        for (int dy2 = 0; dy2 < 2; dy2++)
#pragma unroll
            for (int dx2 = 0; dx2 < 2; dx2++) {
                int iy = y0 + dy2, ix = x0 + dx2;
                if ((unsigned)iy < 64u && (unsigned)ix < 64u) {
                    float wg = (dy2 ? wy1 : 1.0f - wy1) * (dx2 ? wx1 : 1.0f - wx1);
                    const float4 v = *(const float4*)(g_fq + (((b * HH + iy) * WW + ix) * CH + 4 * lane));
                    qv0 += wg * v.x; qv1 += wg * v.y; qv2 += wg * v.z; qv3 += wg * v.w;
                }
            }
    }

    // one warp-wide sincos: lane = a*16+i computes theta = 2*f_a*fr_i
    {
        int a = lane >> 4, i2 = lane & 15;
        float th = 2.0f * (a ? fx : fy) * sfr[i2];
        float s, c;
        sincosf(th, &s, &c);
        sth[w][a][i2] = s; cth[w][a][i2] = c;
    }
    __syncwarp();
    // lanes 0..13: bias via precomputed angle-addition tables (layout [i][dd][h])
    if (lane < 14) {
        int a = lane / 7;
        float b0 = 0.f, b1 = 0.f, b2 = 0.f, b3 = 0.f;
        const float4* Ap = (const float4*)sA + lane;
        const float4* Bp = (const float4*)sB + lane;
#pragma unroll
        for (int i = 0; i < 16; i++) {
            float s = sth[w][a][i], c = cth[w][a][i];
            float4 Av = Ap[i * 14];
            float4 Bv = Bp[i * 14];
            b0 += s * Av.x + c * Bv.x;
            b1 += s * Av.y + c * Bv.y;
            b2 += s * Av.z + c * Bv.z;
            b3 += s * Av.w + c * Bv.w;
        }
        if (a == 0) { b0 += spbb[0]; b1 += spbb[1]; b2 += spbb[2]; b3 += spbb[3]; }
        int dpos = lane - a * 7;
        sbias[w][a][dpos][0] = b0; sbias[w][a][dpos][1] = b1;
        sbias[w][a][dpos][2] = b2; sbias[w][a][dpos][3] = b3;
    }
    __syncwarp();

    const float scale = 0.17677669529663687f;
    {
        int k = 0;
        for (int dy = -3; dy <= 3; dy++) {
            for (int dx = -3; dx <= 3; dx++, k++) {
                int iy = iy0 + dy, ix = ix0 + dx;
                float dot = 0.0f;
                if ((unsigned)iy < 64u && (unsigned)ix < 64u) {
                    const float4 kv = *(const float4*)(g_fk + (((b * HH + iy) * WW + ix) * CH + 4 * lane));
                    dot = qv0 * kv.x + qv1 * kv.y + qv2 * kv.z + qv3 * kv.w;
                }
                dot += __shfl_xor_sync(0xffffffffu, dot, 1);
                dot += __shfl_xor_sync(0xffffffffu, dot, 2);
                dot += __shfl_xor_sync(0xffffffffu, dot, 4);
                float lg = dot * scale + sbias[w][0][dy + 3][h] + sbias[w][1][dx + 3][h];
                if ((lane & 7) == 0) slog[w][h][k] = lg;
            }
        }
    }
    __syncwarp();

    float mx = -1e30f;
    for (int kk = 0; kk < KAREA; kk++) mx = fmaxf(mx, slog[w][h][kk]);
    float ssum = 0.0f;
    for (int kk = 0; kk < KAREA; kk++) ssum += expf(slog[w][h][kk] - mx);
    float inv = 1.0f / ssum;

    float a0 = 0.f, a1 = 0.f, a2 = 0.f, a3 = 0.f;
    {
        int k = 0;
        for (int dy = -3; dy <= 3; dy++) {
            for (int dx = -3; dx <= 3; dx++, k++) {
                int iy = iy0 + dy, ix = ix0 + dx;
                if ((unsigned)iy < 64u && (unsigned)ix < 64u) {
                    float wg = expf(slog[w][h][k] - mx) * inv;
                    const float4 v = *(const float4*)(g_fv + (((b * HH + iy) * WW + ix) * CH + 4 * lane));
                    a0 += wg * v.x; a1 += wg * v.y; a2 += wg * v.z; a3 += wg * v.w;
                }
            }
        }
    }
    int base = q * CH + 4 * lane;
    __nv_bfloat16 h0, l0, h1, l1, h2, l2, h3, l3;
    split_hl(a0, h0, l0); split_hl(a1, h1, l1);
    split_hl(a2, h2, l2); split_hl(a3, h3, l3);
    __nv_bfloat162 p;
    p.x = h0; p.y = h1; *(__nv_bfloat162*)(g_aggh + base) = p;
    p.x = h2; p.y = h3; *(__nv_bfloat162*)(g_aggh + base + 2) = p;
    p.x = l0; p.y = l1; *(__nv_bfloat162*)(g_aggl + base) = p;
    p.x = l2; p.y = l3; *(__nv_bfloat162*)(g_aggl + base + 2) = p;
}

// ---------------- MLP via split-bf16 mma, 128 q/block (single wave), cp.async ----------------
#define MLP_SMEM 208896
__global__ __launch_bounds__(512, 1) void mlpmma_kernel(const float* __restrict__ coord,
                                                        const float* __restrict__ b1,
                                                        float* __restrict__ out) {
    extern __shared__ char sm8[];
    unsigned sb = sptr(sm8);
    int t = threadIdx.x, lane = t & 31, w = t >> 5;
    int mw = w >> 2, nw = w & 3;
    int qbase = blockIdx.x * 128;
    int b = qbase / QPB;

    int arow = (lane & 15);
    int acoloff = ((lane >> 4) << 3);
    int brow = ((lane >> 4) << 3) + (lane & 7);
    int bcoloff = ((lane >> 3) & 1) * 8;

#pragma unroll
    for (int i = 0; i < 8; i++) {
        int e = t + i * 512;
        int half = e >> 11; int idx = e & 2047; int r = idx >> 4; int seg = idx & 15;
        const __nv_bfloat16* src = (half ? g_aggl : g_aggh) + (qbase + r) * 128 + seg * 8;
        CP_ASYNC16(sb + (unsigned)(half * 34816 + r * 272 + seg * 16), src, 16);
    }
#pragma unroll
    for (int i = 0; i < 16; i++) {
        int e = t + i * 512;
        int half = e >> 12; int idx = e & 4095; int j = idx >> 4; int seg = idx & 15;
        const __nv_bfloat16* src = (half ? g_w0l : g_w0h) + j * 128 + seg * 8;
        CP_ASYNC16(sb + (unsigned)(69632 + half * 69632 + j * 272 + seg * 16), src, 16);
    }
    CP_COMMIT();

    float acc1[2][8][4];
#pragma unroll
    for (int mi = 0; mi < 2; mi++)
#pragma unroll
        for (int n = 0; n < 8; n++)
#pragma unroll
            for (int r = 0; r < 4; r++) acc1[mi][n][r] = 0.0f;

    CP_WAIT0();
    __syncthreads();

#pragma unroll
    for (int ksub = 0; ksub < 8; ksub++) {
        unsigned ah[2][4], al[2][4];
        int kg = ksub * 16 + acoloff;
#pragma unroll
        for (int mi = 0; mi < 2; mi++) {
            unsigned aaddr = sb + (unsigned)((mw * 32 + mi * 16 + arow) * 272 + kg * 2);
            LDMX4(ah[mi], aaddr);
            LDMX4(al[mi], aaddr + 34816u);
        }
#pragma unroll
        for (int nt = 0; nt < 4; nt++) {
            unsigned baddr = sb + 69632u +
                (unsigned)((nw * 64 + nt * 16 + brow) * 272 + (bcoloff + ksub * 16) * 2);
            unsigned bh[4], bl[4];
            LDMX4(bh, baddr);
            LDMX4(bl, baddr + 69632u);
#pragma unroll
            for (int mi = 0; mi < 2; mi++)
#pragma unroll
                for (int h = 0; h < 2; h++) {
                    float* d = acc1[mi][nt * 2 + h];
                    MMA16816(d, ah[mi], bh[2 * h], bh[2 * h + 1]);
                    MMA16816(d, ah[mi], bl[2 * h], bl[2 * h + 1]);
                    MMA16816(d, al[mi], bh[2 * h], bh[2 * h + 1]);
                }
        }
    }
    __syncthreads();

#pragma unroll
    for (int i = 0; i < 8; i++) {
        int e = t + i * 512;
        int half = e >> 11; int idx = e & 2047; int o = idx >> 4; int seg = idx & 15;
        const __nv_bfloat16* src = (half ? g_w1l : g_w1h) + o * 256 + seg * 8;
        CP_ASYNC16(sb + (unsigned)(135168 + half * 34816 + o * 272 + seg * 16), src, 16);
    }
    CP_COMMIT();

    {
        int r0 = mw * 32 + (lane >> 2);
        int cb = nw * 64 + (lane & 3) * 2;
#pragma unroll
        for (int mi = 0; mi < 2; mi++) {
#pragma unroll
            for (int n = 0; n < 8; n++) {
                int c = cb + n * 8;
                float c0a = g_c0[b * 256 + c];
                float c0b = g_c0[b * 256 + c + 1];
#pragma unroll
                for (int rs = 0; rs < 2; rs++) {
                    float v0 = acc1[mi][n][rs * 2 + 0] + c0a;
                    float v1 = acc1[mi][n][rs * 2 + 1] + c0b;
                    float gl0 = 0.5f * v0 * (1.0f + erff(v0 * 0.70710678118654752f));
                    float gl1 = 0.5f * v1 * (1.0f + erff(v1 * 0.70710678118654752f));
                    __nv_bfloat16 h0, l0, h1, l1;
                    split_hl(gl0, h0, l0); split_hl(gl1, h1, l1);
                    int row = r0 + mi * 16 + rs * 8;
                    __nv_bfloat162 hp; hp.x = h0; hp.y = h1;
                    __nv_bfloat162 lp; lp.x = l0; lp.y = l1;
                    *(__nv_bfloat162*)(sm8 + row * 528 + c * 2) = hp;
                    *(__nv_bfloat162*)(sm8 + 67584 + row * 528 + c * 2) = lp;
                }
            }
        }
    }

    float acc2[2][2][2][4];
#pragma unroll
    for (int mi = 0; mi < 2; mi++)
#pragma unroll
        for (int nt = 0; nt < 2; nt++)
#pragma unroll
            for (int h = 0; h < 2; h++)
#pragma unroll
                for (int r = 0; r < 4; r++) acc2[mi][nt][h][r] = 0.0f;

    for (int kc = 0; kc < 2; kc++) {
        CP_WAIT0();
        __syncthreads();
#pragma unroll
        for (int ksub = 0; ksub < 8; ksub++) {
            unsigned ah[2][4], al[2][4];
            int kg = kc * 128 + ksub * 16 + acoloff;
#pragma unroll
            for (int mi = 0; mi < 2; mi++) {
                unsigned aaddr = sb + (unsigned)((mw * 32 + mi * 16 + arow) * 528 + kg * 2);
                LDMX4(ah[mi], aaddr);
                LDMX4(al[mi], aaddr + 67584u);
            }
#pragma unroll
            for (int nt = 0; nt < 2; nt++) {
                unsigned baddr = sb + 135168u +
                    (unsigned)((nw * 32 + nt * 16 + brow) * 272 + (bcoloff + ksub * 16) * 2);
                unsigned bh[4], bl[4];
                LDMX4(bh, baddr);
                LDMX4(bl, baddr + 34816u);
#pragma unroll
                for (int mi = 0; mi < 2; mi++)
#pragma unroll
                    for (int h = 0; h < 2; h++) {
                        float* d = acc2[mi][nt][h];
                        MMA16816(d, ah[mi], bh[2 * h], bh[2 * h + 1]);
                        MMA16816(d, ah[mi], bl[2 * h], bl[2 * h + 1]);
                        MMA16816(d, al[mi], bh[2 * h], bh[2 * h + 1]);
                    }
            }
        }
        if (kc == 0) {
            __syncthreads();
#pragma unroll
            for (int i = 0; i < 8; i++) {
                int e = t + i * 512;
                int half = e >> 11; int idx = e & 2047; int o = idx >> 4; int seg = idx & 15;
                const __nv_bfloat16* src = (half ? g_w1l : g_w1h) + o * 256 + 128 + seg * 8;
                CP_ASYNC16(sb + (unsigned)(135168 + half * 34816 + o * 272 + seg * 16), src, 16);
            }
            CP_COMMIT();
        }
    }

#pragma unroll
    for (int mi = 0; mi < 2; mi++) {
#pragma unroll
        for (int rs = 0; rs < 2; rs++) {
            int q = qbase + mw * 32 + mi * 16 + (lane >> 2) + rs * 8;
            float cy = coord[q * 2 + 0];
            float cx = coord[q * 2 + 1];
            float py = fminf(fmaxf(((cy + 1.0f) * 64.0f - 1.0f) * 0.5f, 0.0f), 63.0f);
            float px = fminf(fmaxf(((cx + 1.0f) * 64.0f - 1.0f) * 0.5f, 0.0f), 63.0f);
            float yf = floorf(py), xf = floorf(px);
            int y0 = (int)yf, x0 = (int)xf;
            float wy1 = py - yf, wx1 = px - xf;
            int y1 = min(y0 + 1, 63), x1 = min(x0 + 1, 63);
            float wts[4] = { (1.0f - wy1) * (1.0f - wx1), (1.0f - wy1) * wx1,
                             wy1 * (1.0f - wx1),          wy1 * wx1 };
            const float* fp0 = g_ft + ((b * HH + y0) * WW + x0) * CH;
            const float* fp1 = g_ft + ((b * HH + y0) * WW + x1) * CH;
            const float* fp2 = g_ft + ((b * HH + y1) * WW + x0) * CH;
            const float* fp3 = g_ft + ((b * HH + y1) * WW + x1) * CH;
#pragma unroll
            for (int nt = 0; nt < 2; nt++) {
#pragma unroll
                for (int h = 0; h < 2; h++) {
                    int c = nw * 32 + nt * 16 + h * 8 + (lane & 3) * 2;
                    float2 f0 = *(const float2*)(fp0 + c);
                    float2 f1 = *(const float2*)(fp1 + c);
                    float2 f2 = *(const float2*)(fp2 + c);
                    float2 f3 = *(const float2*)(fp3 + c);
                    float s0 = wts[0] * f0.x + wts[1] * f1.x + wts[2] * f2.x + wts[3] * f3.x;
                    float s1 = wts[0] * f0.y + wts[1] * f1.y + wts[2] * f2.y + wts[3] * f3.y;
                    float2 o;
                    o.x = acc2[mi][nt][h][rs * 2 + 0] + b1[c] + s0;
                    o.y = acc2[mi][nt][h][rs * 2 + 1] + b1[c + 1] + s1;
                    *(float2*)(out + q * CH + c) = o;
                }
            }
        }
    }
}

// ---------------- launch ----------------
typedef CUresult (*EncTiledFn)(CUtensorMap*, CUtensorMapDataType, cuuint32_t, void*,
                               const cuuint64_t*, const cuuint64_t*, const cuuint32_t*,
                               const cuuint32_t*, CUtensorMapInterleave, CUtensorMapSwizzle,
                               CUtensorMapL2promotion, CUtensorMapFloatOOBfill);

extern "C" void kernel_launch(void* const* d_in, const int* in_sizes, int n_in,
                              void* d_out, int out_size) {
    const float* x     = (const float*)d_in[0];
    const float* coord = (const float*)d_in[1];
    const float* cell  = (const float*)d_in[3];
    const float* qw    = (const float*)d_in[4];
    const float* qb    = (const float*)d_in[5];
    const float* kw    = (const float*)d_in[6];
    const float* kb    = (const float*)d_in[7];
    const float* vw    = (const float*)d_in[8];
    const float* vb    = (const float*)d_in[9];
    const float* pbw   = (const float*)d_in[10];
    const float* pbb   = (const float*)d_in[11];
    const float* w0    = (const float*)d_in[12];
    const float* b0    = (const float*)d_in[13];
    const float* w1    = (const float*)d_in[14];
    const float* b1    = (const float*)d_in[15];
    float* out = (float*)d_out;

    void* fp = nullptr;
    cudaGetDriverEntryPoint("cuTensorMapEncodeTiled", &fp, cudaEnableDefault, nullptr);
    EncTiledFn enc = (EncTiledFn)fp;

    void *pxh, *pxl, *pwh, *pwl;
    cudaGetSymbolAddress(&pxh, g_xh2);
    cudaGetSymbolAddress(&pxl, g_xl2);
    cudaGetSymbolAddress(&pwh, g_wh2);
    cudaGetSymbolAddress(&pwl, g_wl2);

    CUtensorMap mxh, mxl, mwh, mwl;
    {
        cuuint64_t dims[5]    = {64, 64, 64, 2, 2};
        cuuint64_t strides[4] = {128, 8192, 524288, 1048576};
        cuuint32_t box[5]     = {64, 64, 2, 1, 1};
        cuuint32_t es[5]      = {1, 1, 1, 1, 1};
        enc(&mxh, CU_TENSOR_MAP_DATA_TYPE_BFLOAT16, 5, pxh, dims, strides, box, es,
            CU_TENSOR_MAP_INTERLEAVE_NONE, CU_TENSOR_MAP_SWIZZLE_128B,
            CU_TENSOR_MAP_L2_PROMOTION_L2_128B, CU_TENSOR_MAP_FLOAT_OOB_FILL_NONE);
        enc(&mxl, CU_TENSOR_MAP_DATA_TYPE_BFLOAT16, 5, pxl, dims, strides, box, es,
            CU_TENSOR_MAP_INTERLEAVE_NONE, CU_TENSOR_MAP_SWIZZLE_128B,
            CU_TENSOR_MAP_L2_PROMOTION_L2_128B, CU_TENSOR_MAP_FLOAT_OOB_FILL_NONE);
    }
    {
        cuuint64_t dims[3]    = {64, 3456, 2};
        cuuint64_t strides[2] = {128, 442368};
        cuuint32_t box[3]     = {64, 64, 1};
        cuuint32_t es[3]      = {1, 1, 1};
        enc(&mwh, CU_TENSOR_MAP_DATA_TYPE_BFLOAT16, 3, pwh, dims, strides, box, es,
            CU_TENSOR_MAP_INTERLEAVE_NONE, CU_TENSOR_MAP_SWIZZLE_128B,
            CU_TENSOR_MAP_L2_PROMOTION_L2_128B, CU_TENSOR_MAP_FLOAT_OOB_FILL_NONE);
        enc(&mwl, CU_TENSOR_MAP_DATA_TYPE_BFLOAT16, 3, pwl, dims, strides, box, es,
            CU_TENSOR_MAP_INTERLEAVE_NONE, CU_TENSOR_MAP_SWIZZLE_128B,
            CU_TENSOR_MAP_L2_PROMOTION_L2_128B, CU_TENSOR_MAP_FLOAT_OOB_FILL_NONE);
    }

    prep_w_kernel<<<(3 * 9 * CH * CH + 255) / 256, 256>>>(qw, kw, vw);
    prep_x_kernel<<<(BATCH * HH * WW * CH + 255) / 256, 256>>>(x);
    prep_small_kernel<<<(66064 + 1792 + 255) / 256, 256>>>(w0, b0, w1, cell, pbw);

    cudaFuncSetAttribute(convtma_kernel, cudaFuncAttributeMaxDynamicSharedMemorySize, CONV_SMEM_ALLOC);
    convtma_kernel<<<dim3(32, 2, 6), 256, CONV_SMEM_ALLOC>>>(mxh, mxl, mwh, mwl, qb, kb, vb);

    attn_kernel<<<NQ / 8, 256>>>(coord, pbb);

    cudaFuncSetAttribute(mlpmma_kernel, cudaFuncAttributeMaxDynamicSharedMemorySize, MLP_SMEM);
    mlpmma_kernel<<<NQ / 128, 512, MLP_SMEM>>>(coord, b1, out);
}

// round 14
// speedup vs baseline: 1.4570x; 1.0715x over previous
#include <cuda_runtime.h>
#include <cuda.h>
#include <cuda_bf16.h>
#include <math.h>

#define BATCH 2
#define CH    128
#define HH    64
#define WW    64
#define QPB   9216
#define NQ    18432
#define NHEAD 4
#define KWIN  7
#define KAREA 49

// ---------------- scratch (static device memory; no allocation) ----------------
__device__ float g_ft[BATCH*HH*WW*CH];          // feat NHWC (for skip)
__device__ float g_fq[BATCH*HH*WW*CH];          // conv q NHWC
__device__ float g_fk[BATCH*HH*WW*CH];          // conv k NHWC
__device__ float g_fv[BATCH*HH*WW*CH];          // conv v NHWC
// input, TMA layout: [cic(2)][b(2)][y(64)][x(64)][c64]
__device__ __align__(1024) __nv_bfloat16 g_xh2[2*BATCH*HH*WW*64];
__device__ __align__(1024) __nv_bfloat16 g_xl2[2*BATCH*HH*WW*64];
// conv weights, TMA layout: [cic(2)][row=(z*9+kk)*128+co (3456)][ci64]
__device__ __align__(1024) __nv_bfloat16 g_wh2[2*3456*64];
__device__ __align__(1024) __nv_bfloat16 g_wl2[2*3456*64];
__device__ __nv_bfloat16 g_w0h[256*128];        // w0 [j][k] hi (k<128)
__device__ __nv_bfloat16 g_w0l[256*128];
__device__ __nv_bfloat16 g_w1h[128*256];        // w1 [o][k] hi
__device__ __nv_bfloat16 g_w1l[128*256];
__device__ float g_c0[2*256];                   // per-batch effective hidden bias
__device__ float g_fr16[16];                    // fp32 freqs
__device__ float g_pbA[16*14*4];                // angle-addition tables [i][a*7+d][h]
__device__ float g_pbB[16*14*4];
__device__ __nv_bfloat16 g_aggh[NQ*CH];         // attention output hi
__device__ __nv_bfloat16 g_aggl[NQ*CH];         // lo

static __device__ __forceinline__ void split_hl(float v, __nv_bfloat16& h, __nv_bfloat16& l) {
    h = __float2bfloat16_rn(v);
    l = __float2bfloat16_rn(v - __bfloat162float(h));
}

static __device__ __forceinline__ unsigned sptr(const void* p) {
    return (unsigned)__cvta_generic_to_shared(p);
}

#define CP_ASYNC16(dst, src, sz) \
    asm volatile("cp.async.cg.shared.global [%0], [%1], 16, %2;" :: "r"(dst), "l"(src), "r"(sz))
#define CP_COMMIT() asm volatile("cp.async.commit_group;")
#define CP_WAIT0()  asm volatile("cp.async.wait_group 0;")

#define LDMX4(r, addr) \
    asm volatile("ldmatrix.sync.aligned.m8n8.x4.shared.b16 {%0,%1,%2,%3}, [%4];" \
                 : "=r"((r)[0]), "=r"((r)[1]), "=r"((r)[2]), "=r"((r)[3]) : "r"(addr))

#define MMA16816(d, a, b0v, b1v) \
    asm volatile("mma.sync.aligned.m16n8k16.row.col.f32.bf16.bf16.f32 " \
                 "{%0,%1,%2,%3},{%4,%5,%6,%7},{%8,%9},{%0,%1,%2,%3};" \
                 : "+f"((d)[0]), "+f"((d)[1]), "+f"((d)[2]), "+f"((d)[3]) \
                 : "r"((a)[0]), "r"((a)[1]), "r"((a)[2]), "r"((a)[3]), "r"(b0v), "r"(b1v))

static __device__ __forceinline__ void mbar_wait(unsigned mbar, unsigned parity) {
    asm volatile(
        "{\n\t.reg .pred P;\n\t"
        "WL_%=:\n\t"
        "mbarrier.try_wait.parity.acquire.cta.shared::cta.b64 P, [%0], %1, 0x989680;\n\t"
        "@P bra.uni WD_%=;\n\t"
        "bra.uni WL_%=;\n\t"
        "WD_%=:\n\t}"
        :: "r"(mbar), "r"(parity) : "memory");
}

// ---------------- fused prep kernel ----------------
#define PREP_W_N  (3*9*CH*CH)          // 442368
#define PREP_X_N  (BATCH*HH*WW*CH)     // 1048576
#define PREP_S_N  (66064 + 1792)
#define PREP_TOTAL (PREP_W_N + PREP_X_N + PREP_S_N)

__global__ void prep_all_kernel(const float* __restrict__ qw,
                                const float* __restrict__ kw,
                                const float* __restrict__ vw,
                                const float* __restrict__ x,
                                const float* __restrict__ w0,
                                const float* __restrict__ b0,
                                const float* __restrict__ w1,
                                const float* __restrict__ cell,
                                const float* __restrict__ pbw) {
    int gid = blockIdx.x * blockDim.x + threadIdx.x;
    if (gid < PREP_W_N) {
        int idx = gid;
        int ci = idx & 127;
        int co = (idx >> 7) & 127;
        int kk = (idx >> 14) % 9;
        int z  = idx / (9 * CH * CH);
        const float* w = (z == 0) ? qw : ((z == 1) ? kw : vw);
        float v = w[(co * CH + ci) * 9 + kk];
        int row = (z * 9 + kk) * 128 + co;
        int off = (ci >> 6) * (3456 * 64) + row * 64 + (ci & 63);
        split_hl(v, g_wh2[off], g_wl2[off]);
        return;
    }
    gid -= PREP_W_N;
    if (gid < PREP_X_N) {
        int idx = gid;
        int c = idx & 127;
        int p = (idx >> 7) & 4095;
        int b = idx >> 19;
        float v = x[(b * CH + c) * (HH * WW) + p];
        g_ft[idx] = v;
        int off = ((((c >> 6) * 2 + b) * 4096) + p) * 64 + (c & 63);
        split_hl(v, g_xh2[off], g_xl2[off]);
        return;
    }
    int idx = gid - PREP_X_N;
    if (idx < 32768) {
        int j = idx >> 7, k = idx & 127;
        split_hl(w0[j * 130 + k], g_w0h[idx], g_w0l[idx]);
    } else if (idx < 65536) {
        int r = idx - 32768;
        split_hl(w1[r], g_w1h[r], g_w1l[r]);
    } else if (idx < 66048) {
        int r = idx - 65536;
        int b = r / 256, j = r % 256;
        float rc0 = cell[b * 2 + 0] * 64.0f;
        float rc1 = cell[b * 2 + 1] * 64.0f;
        g_c0[r] = b0[j] + w0[j * 130 + 128] * rc0 + w0[j * 130 + 129] * rc1;
    } else if (idx < 66064) {
        int i = idx - 66048;
        const float step = 10.0f / 15.0f;
        g_fr16[i] = (i == 15) ? 1023.0f : (exp2f((float)i * step) - 1.0f);
    } else if (idx < 66064 + 2 * 16 * 14 * 4) {
        int r = idx - 66064;
        int half = r / 896;
        int rr = r - half * 896;
        int i = rr / 56;
        int dd = (rr % 56) / 4;
        int h = rr & 3;
        int a = dd / 7, dpos = dd - a * 7;
        const float step = 10.0f / 15.0f;
        float fr = (i == 15) ? 1023.0f : (exp2f((float)i * step) - 1.0f);
        double phi = 2.0 * (double)(dpos - 3) * (double)fr;
        float cphi = (float)cos(phi);
        float sphi = (float)sin(phi);
        float ws = pbw[h * 64 + a * 16 + i];
        float wc = pbw[h * 64 + 32 + a * 16 + i];
        float val = half ? (wc * cphi - ws * sphi) : (ws * cphi + wc * sphi);
        (half ? g_pbB : g_pbA)[(i * 14 + dd) * 4 + h] = val;
    }
}

// ---------------- conv3x3: TMA 2-stage ring, 2 CTAs/SM, split-bf16 mma ----------------
#define CONV_STAGE 49152
#define CONV_SMEM  (2*CONV_STAGE)
#define CONV_SMEM_ALLOC (CONV_SMEM + 1024)

__device__ __forceinline__ void conv_issue(int s, unsigned dstb, unsigned mbar,
                                           const CUtensorMap* mxh, const CUtensorMap* mxl,
                                           const CUtensorMap* mwh, const CUtensorMap* mwl,
                                           int b, int yt, int z, int nhalf) {
    int kk = s >> 1, cic = s & 1;
    int dy = kk / 3 - 1, dx = kk - (kk / 3) * 3 - 1;
    int ycoord = 2 * yt + dy;
    int wrow = (z * 9 + kk) * 128 + nhalf * 64;
    asm volatile("mbarrier.arrive.expect_tx.shared.b64 _, [%0], %1;"
                 :: "r"(mbar), "r"(49152) : "memory");
#define TMA5D(dst, map, c0, c1, c2, c3, c4) \
    asm volatile("cp.async.bulk.tensor.5d.shared::cta.global.tile.mbarrier::complete_tx::bytes " \
                 "[%0], [%1, {%2,%3,%4,%5,%6}], [%7];" \
                 :: "r"(dst), "l"(map), "r"(c0), "r"(c1), "r"(c2), "r"(c3), "r"(c4), "r"(mbar) : "memory")
#define TMA3D(dst, map, c0, c1, c2) \
    asm volatile("cp.async.bulk.tensor.3d.shared::cta.global.tile.mbarrier::complete_tx::bytes " \
                 "[%0], [%1, {%2,%3,%4}], [%5];" \
                 :: "r"(dst), "l"(map), "r"(c0), "r"(c1), "r"(c2), "r"(mbar) : "memory")
    TMA5D(dstb,          mxh, 0, dx, ycoord, b, cic);
    TMA5D(dstb + 16384u, mxl, 0, dx, ycoord, b, cic);
    TMA3D(dstb + 32768u, mwh, 0, wrow, cic);
    TMA3D(dstb + 40960u, mwl, 0, wrow, cic);
#undef TMA5D
#undef TMA3D
}

__global__ __launch_bounds__(256, 2) void convtma_kernel(
    const __grid_constant__ CUtensorMap mxh,
    const __grid_constant__ CUtensorMap mxl,
    const __grid_constant__ CUtensorMap mwh,
    const __grid_constant__ CUtensorMap mwl,
    const float* __restrict__ qb,
    const float* __restrict__ kb,
    const float* __restrict__ vb) {
    extern __shared__ char smc[];
    __shared__ __align__(8) unsigned long long s_mbar[2];

    int t = threadIdx.x;
    int lane = t & 31;
    int w = t >> 5;
    int yt = blockIdx.x;
    int b  = blockIdx.y;
    int zz = blockIdx.z;
    int z  = zz >> 1;
    int nhalf = zz & 1;

    const float* bias = (z == 0) ? qb : ((z == 1) ? kb : vb);
    float* outp = (z == 0) ? g_fq : ((z == 1) ? g_fk : g_fv);

    int Mbase = (w >> 1) * 32;
    int Nbase = (w & 1) * 32;
    unsigned sb = (sptr(smc) + 1023u) & ~1023u;
    unsigned mb0 = sptr(s_mbar);

    if (t == 0) {
#pragma unroll
        for (int i = 0; i < 2; i++)
            asm volatile("mbarrier.init.shared.b64 [%0], 1;" :: "r"(mb0 + i * 8) : "memory");
        asm volatile("fence.proxy.async.shared::cta;" ::: "memory");
    }
    __syncthreads();

    if (t == 0) {
        conv_issue(0, sb, mb0, &mxh, &mxl, &mwh, &mwl, b, yt, z, nhalf);
        conv_issue(1, sb + CONV_STAGE, mb0 + 8, &mxh, &mxl, &mwh, &mwl, b, yt, z, nhalf);
    }

    float acc[2][4][4];
#pragma unroll
    for (int mi = 0; mi < 2; mi++)
#pragma unroll
        for (int ni = 0; ni < 4; ni++)
#pragma unroll
            for (int r = 0; r < 4; r++) acc[mi][ni][r] = 0.0f;

    int arow = (lane & 15);
    int acolb = ((lane >> 4) << 3) * 2;
    int brow = ((lane >> 4) << 3) + (lane & 7);
    int bcolb = (((lane >> 3) & 1) * 8) * 2;

    for (int s = 0; s < 18; s++) {
        int slot = s & 1;
        mbar_wait(mb0 + slot * 8, (unsigned)((s >> 1) & 1));
        unsigned bufb = sb + (unsigned)slot * CONV_STAGE;
#pragma unroll
        for (int ksub = 0; ksub < 4; ksub++) {
            unsigned ah[2][4], al[2][4];
#pragma unroll
            for (int mi = 0; mi < 2; mi++) {
                int p = Mbase + mi * 16 + arow;
                unsigned aoff = (unsigned)(p * 128 + ((acolb + ksub * 32) ^ ((p & 7) << 4)));
                LDMX4(ah[mi], bufb + aoff);
                LDMX4(al[mi], bufb + 16384u + aoff);
            }
#pragma unroll
            for (int nt = 0; nt < 2; nt++) {
                int n = Nbase + nt * 16 + brow;
                unsigned boff = (unsigned)(n * 128 + ((bcolb + ksub * 32) ^ ((n & 7) << 4)));
                unsigned bh[4], bl[4];
                LDMX4(bh, bufb + 32768u + boff);
                LDMX4(bl, bufb + 40960u + boff);
#pragma unroll
                for (int mi = 0; mi < 2; mi++) {
#pragma unroll
                    for (int h = 0; h < 2; h++) {
                        float* d = acc[mi][nt * 2 + h];
                        MMA16816(d, ah[mi], bh[2 * h], bh[2 * h + 1]);
                        MMA16816(d, ah[mi], bl[2 * h], bl[2 * h + 1]);
                        MMA16816(d, al[mi], bh[2 * h], bh[2 * h + 1]);
                    }
                }
            }
        }
        __syncthreads();
        if (s + 2 < 18 && t == 0)
            conv_issue(s + 2, sb + (unsigned)slot * CONV_STAGE, mb0 + slot * 8,
                       &mxh, &mxl, &mwh, &mwl, b, yt, z, nhalf);
    }

    int rr = lane >> 2;
    int c2 = (lane & 3) * 2;
#pragma unroll
    for (int mi = 0; mi < 2; mi++) {
#pragma unroll
        for (int ni = 0; ni < 4; ni++) {
            int co = nhalf * 64 + Nbase + ni * 8 + c2;
            float b0v = bias[co], b1v = bias[co + 1];
#pragma unroll
            for (int rs = 0; rs < 2; rs++) {
                int p = Mbase + mi * 16 + rr + rs * 8;
                int r = p >> 6, xo = p & 63;
                float* o = outp + ((b * HH + yt * 2 + r) * WW + xo) * CH + co;
                *(float2*)o = make_float2(acc[mi][ni][rs * 2 + 0] + b0v,
                                          acc[mi][ni][rs * 2 + 1] + b1v);
            }
        }
    }
}

// ---------------- attention: one warp per query, cooperative softmax ----------------
__global__ __launch_bounds__(256) void attn_kernel(const float* __restrict__ coord,
                                                   const float* __restrict__ pbb) {
    __shared__ float slog[8][NHEAD][KAREA];
    __shared__ float sbias[8][2][KWIN][NHEAD];
    __shared__ float spbb[NHEAD];
    __shared__ float sfr[16];
    __shared__ float sA[16*14*4];
    __shared__ float sB[16*14*4];
    __shared__ float sth[8][2][16];
    __shared__ float cth[8][2][16];

    int t = threadIdx.x;
    int w = t >> 5;
    int lane = t & 31;
    if (t < NHEAD) spbb[t] = pbb[t];
    if (t < 16) sfr[t] = g_fr16[t];
    for (int i = t; i < 16 * 14 * 4; i += 256) { sA[i] = g_pbA[i]; sB[i] = g_pbB[i]; }
    __syncthreads();

    int q = blockIdx.x * 8 + w;
    int b = q / QPB;
    float cy = coord[q * 2 + 0];
    float cx = coord[q * 2 + 1];
    float py = ((cy + 1.0f) * 64.0f - 1.0f) * 0.5f;
    float px = ((cx + 1.0f) * 64.0f - 1.0f) * 0.5f;
    float riy = rintf(py), rix = rintf(px);
    int iy0 = (int)riy, ix0 = (int)rix;
    float fy = py - riy, fx = px - rix;
    int h = lane >> 3;

    float qv0 = 0.f, qv1 = 0.f, qv2 = 0.f, qv3 = 0.f;
    {
        float yf = floorf(py), xf = floorf(px);
        int y0 = (int)yf, x0 = (int)xf;
        float wy1 = py - yf, wx1 = px - xf;
#pragma unroll
        for (int dy2 = 0; dy2 < 2; dy2++)
#pragma unroll
            for (int dx2 = 0; dx2 < 2; dx2++) {
                int iy = y0 + dy2, ix = x0 + dx2;
                if ((unsigned)iy < 64u && (unsigned)ix < 64u) {
                    float wg = (dy2 ? wy1 : 1.0f - wy1) * (dx2 ? wx1 : 1.0f - wx1);
                    const float4 v = *(const float4*)(g_fq + (((b * HH + iy) * WW + ix) * CH + 4 * lane));
                    qv0 += wg * v.x; qv1 += wg * v.y; qv2 += wg * v.z; qv3 += wg * v.w;
                }
            }
    }

    // one warp-wide sincos: lane = a*16+i computes theta = 2*f_a*fr_i
    {
        int a = lane >> 4, i2 = lane & 15;
        float th = 2.0f * (a ? fx : fy) * sfr[i2];
        float s, c;
        sincosf(th, &s, &c);
        sth[w][a][i2] = s; cth[w][a][i2] = c;
    }
    __syncwarp();
    // lanes 0..13: bias via precomputed angle-addition tables (layout [i][dd][h])
    if (lane < 14) {
        int a = lane / 7;
        float b0 = 0.f, b1 = 0.f, b2 = 0.f, b3 = 0.f;
        const float4* Ap = (const float4*)sA + lane;
        const float4* Bp = (const float4*)sB + lane;
#pragma unroll
        for (int i = 0; i < 16; i++) {
            float s = sth[w][a][i], c = cth[w][a][i];
            float4 Av = Ap[i * 14];
            float4 Bv = Bp[i * 14];
            b0 += s * Av.x + c * Bv.x;
            b1 += s * Av.y + c * Bv.y;
            b2 += s * Av.z + c * Bv.z;
            b3 += s * Av.w + c * Bv.w;
        }
        if (a == 0) { b0 += spbb[0]; b1 += spbb[1]; b2 += spbb[2]; b3 += spbb[3]; }
        int dpos = lane - a * 7;
        sbias[w][a][dpos][0] = b0; sbias[w][a][dpos][1] = b1;
        sbias[w][a][dpos][2] = b2; sbias[w][a][dpos][3] = b3;
    }
    __syncwarp();

    const float scale = 0.17677669529663687f;
    {
        int k = 0;
        for (int dy = -3; dy <= 3; dy++) {
            for (int dx = -3; dx <= 3; dx++, k++) {
                int iy = iy0 + dy, ix = ix0 + dx;
                float dot = 0.0f;
                if ((unsigned)iy < 64u && (unsigned)ix < 64u) {
                    const float4 kv = *(const float4*)(g_fk + (((b * HH + iy) * WW + ix) * CH + 4 * lane));
                    dot = qv0 * kv.x + qv1 * kv.y + qv2 * kv.z + qv3 * kv.w;
                }
                dot += __shfl_xor_sync(0xffffffffu, dot, 1);
                dot += __shfl_xor_sync(0xffffffffu, dot, 2);
                dot += __shfl_xor_sync(0xffffffffu, dot, 4);
                float lg = dot * scale + sbias[w][0][dy + 3][h] + sbias[w][1][dx + 3][h];
                if ((lane & 7) == 0) slog[w][h][k] = lg;
            }
        }
    }
    __syncwarp();

    // cooperative softmax: 8 lanes of each head-group split the 49 taps
    int sl = lane & 7;
    float mx = -1e30f;
    for (int kk = sl; kk < KAREA; kk += 8) mx = fmaxf(mx, slog[w][h][kk]);
    mx = fmaxf(mx, __shfl_xor_sync(0xffffffffu, mx, 1));
    mx = fmaxf(mx, __shfl_xor_sync(0xffffffffu, mx, 2));
    mx = fmaxf(mx, __shfl_xor_sync(0xffffffffu, mx, 4));
    float lsum = 0.0f;
    for (int kk = sl; kk < KAREA; kk += 8) {
        float e = expf(slog[w][h][kk] - mx);
        slog[w][h][kk] = e;
        lsum += e;
    }
    lsum += __shfl_xor_sync(0xffffffffu, lsum, 1);
    lsum += __shfl_xor_sync(0xffffffffu, lsum, 2);
    lsum += __shfl_xor_sync(0xffffffffu, lsum, 4);
    float inv = 1.0f / lsum;
    __syncwarp();

    float a0 = 0.f, a1 = 0.f, a2 = 0.f, a3 = 0.f;
    {
        int k = 0;
        for (int dy = -3; dy <= 3; dy++) {
            for (int dx = -3; dx <= 3; dx++, k++) {
                int iy = iy0 + dy, ix = ix0 + dx;
                if ((unsigned)iy < 64u && (unsigned)ix < 64u) {
                    float wg = slog[w][h][k] * inv;
                    const float4 v = *(const float4*)(g_fv + (((b * HH + iy) * WW + ix) * CH + 4 * lane));
                    a0 += wg * v.x; a1 += wg * v.y; a2 += wg * v.z; a3 += wg * v.w;
                }
            }
        }
    }
    int base = q * CH + 4 * lane;
    __nv_bfloat16 h0, l0, h1, l1, h2, l2, h3, l3;
    split_hl(a0, h0, l0); split_hl(a1, h1, l1);
    split_hl(a2, h2, l2); split_hl(a3, h3, l3);
    __nv_bfloat162 p;
    p.x = h0; p.y = h1; *(__nv_bfloat162*)(g_aggh + base) = p;
    p.x = h2; p.y = h3; *(__nv_bfloat162*)(g_aggh + base + 2) = p;
    p.x = l0; p.y = l1; *(__nv_bfloat162*)(g_aggl + base) = p;
    p.x = l2; p.y = l3; *(__nv_bfloat162*)(g_aggl + base + 2) = p;
}

// ---------------- MLP via split-bf16 mma, 128 q/block (single wave), cp.async ----------------
#define MLP_SMEM 208896
__global__ __launch_bounds__(512, 1) void mlpmma_kernel(const float* __restrict__ coord,
                                                        const float* __restrict__ b1,
                                                        float* __restrict__ out) {
    extern __shared__ char sm8[];
    unsigned sb = sptr(sm8);
    int t = threadIdx.x, lane = t & 31, w = t >> 5;
    int mw = w >> 2, nw = w & 3;
    int qbase = blockIdx.x * 128;
    int b = qbase / QPB;

    int arow = (lane & 15);
    int acoloff = ((lane >> 4) << 3);
    int brow = ((lane >> 4) << 3) + (lane & 7);
    int bcoloff = ((lane >> 3) & 1) * 8;

#pragma unroll
    for (int i = 0; i < 8; i++) {
        int e = t + i * 512;
        int half = e >> 11; int idx = e & 2047; int r = idx >> 4; int seg = idx & 15;
        const __nv_bfloat16* src = (half ? g_aggl : g_aggh) + (qbase + r) * 128 + seg * 8;
        CP_ASYNC16(sb + (unsigned)(half * 34816 + r * 272 + seg * 16), src, 16);
    }
#pragma unroll
    for (int i = 0; i < 16; i++) {
        int e = t + i * 512;
        int half = e >> 12; int idx = e & 4095; int j = idx >> 4; int seg = idx & 15;
        const __nv_bfloat16* src = (half ? g_w0l : g_w0h) + j * 128 + seg * 8;
        CP_ASYNC16(sb + (unsigned)(69632 + half * 69632 + j * 272 + seg * 16), src, 16);
    }
    CP_COMMIT();

    float acc1[2][8][4];
#pragma unroll
    for (int mi = 0; mi < 2; mi++)
#pragma unroll
        for (int n = 0; n < 8; n++)
#pragma unroll
            for (int r = 0; r < 4; r++) acc1[mi][n][r] = 0.0f;

    CP_WAIT0();
    __syncthreads();

#pragma unroll
    for (int ksub = 0; ksub < 8; ksub++) {
        unsigned ah[2][4], al[2][4];
        int kg = ksub * 16 + acoloff;
#pragma unroll
        for (int mi = 0; mi < 2; mi++) {
            unsigned aaddr = sb + (unsigned)((mw * 32 + mi * 16 + arow) * 272 + kg * 2);
            LDMX4(ah[mi], aaddr);
            LDMX4(al[mi], aaddr + 34816u);
        }
#pragma unroll
        for (int nt = 0; nt < 4; nt++) {
            unsigned baddr = sb + 69632u +
                (unsigned)((nw * 64 + nt * 16 + brow) * 272 + (bcoloff + ksub * 16) * 2);
            unsigned bh[4], bl[4];
            LDMX4(bh, baddr);
            LDMX4(bl, baddr + 69632u);
#pragma unroll
            for (int mi = 0; mi < 2; mi++)
#pragma unroll
                for (int h = 0; h < 2; h++) {
                    float* d = acc1[mi][nt * 2 + h];
                    MMA16816(d, ah[mi], bh[2 * h], bh[2 * h + 1]);
                    MMA16816(d, ah[mi], bl[2 * h], bl[2 * h + 1]);
                    MMA16816(d, al[mi], bh[2 * h], bh[2 * h + 1]);
                }
        }
    }
    __syncthreads();

#pragma unroll
    for (int i = 0; i < 8; i++) {
        int e = t + i * 512;
        int half = e >> 11; int idx = e & 2047; int o = idx >> 4; int seg = idx & 15;
        const __nv_bfloat16* src = (half ? g_w1l : g_w1h) + o * 256 + seg * 8;
        CP_ASYNC16(sb + (unsigned)(135168 + half * 34816 + o * 272 + seg * 16), src, 16);
    }
    CP_COMMIT();

    {
        int r0 = mw * 32 + (lane >> 2);
        int cb = nw * 64 + (lane & 3) * 2;
#pragma unroll
        for (int mi = 0; mi < 2; mi++) {
#pragma unroll
            for (int n = 0; n < 8; n++) {
                int c = cb + n * 8;
                float c0a = g_c0[b * 256 + c];
                float c0b = g_c0[b * 256 + c + 1];
#pragma unroll
                for (int rs = 0; rs < 2; rs++) {
                    float v0 = acc1[mi][n][rs * 2 + 0] + c0a;
                    float v1 = acc1[mi][n][rs * 2 + 1] + c0b;
                    float gl0 = 0.5f * v0 * (1.0f + erff(v0 * 0.70710678118654752f));
                    float gl1 = 0.5f * v1 * (1.0f + erff(v1 * 0.70710678118654752f));
                    __nv_bfloat16 h0, l0, h1, l1;
                    split_hl(gl0, h0, l0); split_hl(gl1, h1, l1);
                    int row = r0 + mi * 16 + rs * 8;
                    __nv_bfloat162 hp; hp.x = h0; hp.y = h1;
                    __nv_bfloat162 lp; lp.x = l0; lp.y = l1;
                    *(__nv_bfloat162*)(sm8 + row * 528 + c * 2) = hp;
                    *(__nv_bfloat162*)(sm8 + 67584 + row * 528 + c * 2) = lp;
                }
            }
        }
    }

    float acc2[2][2][2][4];
#pragma unroll
    for (int mi = 0; mi < 2; mi++)
#pragma unroll
        for (int nt = 0; nt < 2; nt++)
#pragma unroll
            for (int h = 0; h < 2; h++)
#pragma unroll
                for (int r = 0; r < 4; r++) acc2[mi][nt][h][r] = 0.0f;

    for (int kc = 0; kc < 2; kc++) {
        CP_WAIT0();
        __syncthreads();
#pragma unroll
        for (int ksub = 0; ksub < 8; ksub++) {
            unsigned ah[2][4], al[2][4];
            int kg = kc * 128 + ksub * 16 + acoloff;
#pragma unroll
            for (int mi = 0; mi < 2; mi++) {
                unsigned aaddr = sb + (unsigned)((mw * 32 + mi * 16 + arow) * 528 + kg * 2);
                LDMX4(ah[mi], aaddr);
                LDMX4(al[mi], aaddr + 67584u);
            }
#pragma unroll
            for (int nt = 0; nt < 2; nt++) {
                unsigned baddr = sb + 135168u +
                    (unsigned)((nw * 32 + nt * 16 + brow) * 272 + (bcoloff + ksub * 16) * 2);
                unsigned bh[4], bl[4];
                LDMX4(bh, baddr);
                LDMX4(bl, baddr + 34816u);
#pragma unroll
                for (int mi = 0; mi < 2; mi++)
#pragma unroll
                    for (int h = 0; h < 2; h++) {
                        float* d = acc2[mi][nt][h];
                        MMA16816(d, ah[mi], bh[2 * h], bh[2 * h + 1]);
                        MMA16816(d, ah[mi], bl[2 * h], bl[2 * h + 1]);
                        MMA16816(d, al[mi], bh[2 * h], bh[2 * h + 1]);
                    }
            }
        }
        if (kc == 0) {
            __syncthreads();
#pragma unroll
            for (int i = 0; i < 8; i++) {
                int e = t + i * 512;
                int half = e >> 11; int idx = e & 2047; int o = idx >> 4; int seg = idx & 15;
                const __nv_bfloat16* src = (half ? g_w1l : g_w1h) + o * 256 + 128 + seg * 8;
                CP_ASYNC16(sb + (unsigned)(135168 + half * 34816 + o * 272 + seg * 16), src, 16);
            }
            CP_COMMIT();
        }
    }

#pragma unroll
    for (int mi = 0; mi < 2; mi++) {
#pragma unroll
        for (int rs = 0; rs < 2; rs++) {
            int q = qbase + mw * 32 + mi * 16 + (lane >> 2) + rs * 8;
            float cy = coord[q * 2 + 0];
            float cx = coord[q * 2 + 1];
            float py = fminf(fmaxf(((cy + 1.0f) * 64.0f - 1.0f) * 0.5f, 0.0f), 63.0f);
            float px = fminf(fmaxf(((cx + 1.0f) * 64.0f - 1.0f) * 0.5f, 0.0f), 63.0f);
            float yf = floorf(py), xf = floorf(px);
            int y0 = (int)yf, x0 = (int)xf;
            float wy1 = py - yf, wx1 = px - xf;
            int y1 = min(y0 + 1, 63), x1 = min(x0 + 1, 63);
            float wts[4] = { (1.0f - wy1) * (1.0f - wx1), (1.0f - wy1) * wx1,
                             wy1 * (1.0f - wx1),          wy1 * wx1 };
            const float* fp0 = g_ft + ((b * HH + y0) * WW + x0) * CH;
            const float* fp1 = g_ft + ((b * HH + y0) * WW + x1) * CH;
            const float* fp2 = g_ft + ((b * HH + y1) * WW + x0) * CH;
            const float* fp3 = g_ft + ((b * HH + y1) * WW + x1) * CH;
#pragma unroll
            for (int nt = 0; nt < 2; nt++) {
#pragma unroll
                for (int h = 0; h < 2; h++) {
                    int c = nw * 32 + nt * 16 + h * 8 + (lane & 3) * 2;
                    float2 f0 = *(const float2*)(fp0 + c);
                    float2 f1 = *(const float2*)(fp1 + c);
                    float2 f2 = *(const float2*)(fp2 + c);
                    float2 f3 = *(const float2*)(fp3 + c);
                    float s0 = wts[0] * f0.x + wts[1] * f1.x + wts[2] * f2.x + wts[3] * f3.x;
                    float s1 = wts[0] * f0.y + wts[1] * f1.y + wts[2] * f2.y + wts[3] * f3.y;
                    float2 o;
                    o.x = acc2[mi][nt][h][rs * 2 + 0] + b1[c] + s0;
                    o.y = acc2[mi][nt][h][rs * 2 + 1] + b1[c + 1] + s1;
                    *(float2*)(out + q * CH + c) = o;
                }
            }
        }
    }
}

// ---------------- launch ----------------
typedef CUresult (*EncTiledFn)(CUtensorMap*, CUtensorMapDataType, cuuint32_t, void*,
                               const cuuint64_t*, const cuuint64_t*, const cuuint32_t*,
                               const cuuint32_t*, CUtensorMapInterleave, CUtensorMapSwizzle,
                               CUtensorMapL2promotion, CUtensorMapFloatOOBfill);

extern "C" void kernel_launch(void* const* d_in, const int* in_sizes, int n_in,
                              void* d_out, int out_size) {
    const float* x     = (const float*)d_in[0];
    const float* coord = (const float*)d_in[1];
    const float* cell  = (const float*)d_in[3];
    const float* qw    = (const float*)d_in[4];
    const float* qb    = (const float*)d_in[5];
    const float* kw    = (const float*)d_in[6];
    const float* kb    = (const float*)d_in[7];
    const float* vw    = (const float*)d_in[8];
    const float* vb    = (const float*)d_in[9];
    const float* pbw   = (const float*)d_in[10];
    const float* pbb   = (const float*)d_in[11];
    const float* w0    = (const float*)d_in[12];
    const float* b0    = (const float*)d_in[13];
    const float* w1    = (const float*)d_in[14];
    const float* b1    = (const float*)d_in[15];
    float* out = (float*)d_out;

    void* fp = nullptr;
    cudaGetDriverEntryPoint("cuTensorMapEncodeTiled", &fp, cudaEnableDefault, nullptr);
    EncTiledFn enc = (EncTiledFn)fp;

    void *pxh, *pxl, *pwh, *pwl;
    cudaGetSymbolAddress(&pxh, g_xh2);
    cudaGetSymbolAddress(&pxl, g_xl2);
    cudaGetSymbolAddress(&pwh, g_wh2);
    cudaGetSymbolAddress(&pwl, g_wl2);

    CUtensorMap mxh, mxl, mwh, mwl;
    {
        cuuint64_t dims[5]    = {64, 64, 64, 2, 2};
        cuuint64_t strides[4] = {128, 8192, 524288, 1048576};
        cuuint32_t box[5]     = {64, 64, 2, 1, 1};
        cuuint32_t es[5]      = {1, 1, 1, 1, 1};
        enc(&mxh, CU_TENSOR_MAP_DATA_TYPE_BFLOAT16, 5, pxh, dims, strides, box, es,
            CU_TENSOR_MAP_INTERLEAVE_NONE, CU_TENSOR_MAP_SWIZZLE_128B,
            CU_TENSOR_MAP_L2_PROMOTION_L2_128B, CU_TENSOR_MAP_FLOAT_OOB_FILL_NONE);
        enc(&mxl, CU_TENSOR_MAP_DATA_TYPE_BFLOAT16, 5, pxl, dims, strides, box, es,
            CU_TENSOR_MAP_INTERLEAVE_NONE, CU_TENSOR_MAP_SWIZZLE_128B,
            CU_TENSOR_MAP_L2_PROMOTION_L2_128B, CU_TENSOR_MAP_FLOAT_OOB_FILL_NONE);
    }
    {
        cuuint64_t dims[3]    = {64, 3456, 2};
        cuuint64_t strides[2] = {128, 442368};
        cuuint32_t box[3]     = {64, 64, 1};
        cuuint32_t es[3]      = {1, 1, 1};
        enc(&mwh, CU_TENSOR_MAP_DATA_TYPE_BFLOAT16, 3, pwh, dims, strides, box, es,
            CU_TENSOR_MAP_INTERLEAVE_NONE, CU_TENSOR_MAP_SWIZZLE_128B,
            CU_TENSOR_MAP_L2_PROMOTION_L2_128B, CU_TENSOR_MAP_FLOAT_OOB_FILL_NONE);
        enc(&mwl, CU_TENSOR_MAP_DATA_TYPE_BFLOAT16, 3, pwl, dims, strides, box, es,
            CU_TENSOR_MAP_INTERLEAVE_NONE, CU_TENSOR_MAP_SWIZZLE_128B,
            CU_TENSOR_MAP_L2_PROMOTION_L2_128B, CU_TENSOR_MAP_FLOAT_OOB_FILL_NONE);
    }

    prep_all_kernel<<<(PREP_TOTAL + 255) / 256, 256>>>(qw, kw, vw, x, w0, b0, w1, cell, pbw);

    cudaFuncSetAttribute(convtma_kernel, cudaFuncAttributeMaxDynamicSharedMemorySize, CONV_SMEM_ALLOC);
    convtma_kernel<<<dim3(32, 2, 6), 256, CONV_SMEM_ALLOC>>>(mxh, mxl, mwh, mwl, qb, kb, vb);

    attn_kernel<<<NQ / 8, 256>>>(coord, pbb);

    cudaFuncSetAttribute(mlpmma_kernel, cudaFuncAttributeMaxDynamicSharedMemorySize, MLP_SMEM);
    mlpmma_kernel<<<NQ / 128, 512, MLP_SMEM>>>(coord, b1, out);
}